// round 11
// baseline (speedup 1.0000x reference)
#include <cuda_runtime.h>
#include <cuda_fp16.h>
#include <stdint.h>
#include <math.h>

// ---------------- problem constants ----------------
#define B_    8
#define S_    3072
#define H_    12
#define D_    128
#define E_    1536
#define NB_   256
#define CHUNK_ 12
#define CTX_  24
#define MTOK_ (B_*S_)         // 24576

#define OUT_MAIN  ((size_t)MTOK_ * E_)
#define ATTN_SZ   ((size_t)B_*H_*NB_*CHUNK_*CTX_)
#define WELEM_    (E_*E_)

#define QSCALE_BASE (0.088388347648318447f / 0.69314718055994531f)
#define KSCALE      (1.3132616875182228f  / 0.69314718055994531f)

// ---------------- scratch (device globals) ----------------
__device__ float g_q[OUT_MAIN];
__device__ float g_k[OUT_MAIN];
__device__ __half g_vh[OUT_MAIN];          // v projection in fp16
__device__ float g_relk[CTX_ * E_];
__device__ float g_qdscale[D_];

// tiled+swizzled fp16 hi/lo operand storage
__device__ __half g_hs_hi[OUT_MAIN];
__device__ __half g_hs_lo[OUT_MAIN];
__device__ __half g_oc_hi[OUT_MAIN];       // attention output, written tiled+swizzled
__device__ __half g_oc_lo[OUT_MAIN];
__device__ __half g_w_hi[5][WELEM_];
__device__ __half g_w_lo[5][WELEM_];
__device__ __half g_pe_hi[128 * E_];
__device__ __half g_pe_lo[128 * E_];

// ---------------- helpers ----------------
__device__ __forceinline__ void mma_f16(float c[4], unsigned a0, unsigned a1,
                                        unsigned a2, unsigned a3,
                                        unsigned b0, unsigned b1){
    asm volatile(
        "mma.sync.aligned.m16n8k16.row.col.f32.f16.f16.f32 "
        "{%0,%1,%2,%3}, {%4,%5,%6,%7}, {%8,%9}, {%0,%1,%2,%3};"
        : "+f"(c[0]), "+f"(c[1]), "+f"(c[2]), "+f"(c[3])
        : "r"(a0), "r"(a1), "r"(a2), "r"(a3), "r"(b0), "r"(b1));
}
__device__ __forceinline__ void ldsm4(unsigned r[4], unsigned addr){
    asm volatile("ldmatrix.sync.aligned.m8n8.x4.shared.b16 {%0,%1,%2,%3}, [%4];"
                 : "=r"(r[0]), "=r"(r[1]), "=r"(r[2]), "=r"(r[3]) : "r"(addr));
}
__device__ __forceinline__ void bulk_cp(unsigned dst, const void* src, unsigned bytes,
                                        unsigned mbar){
    asm volatile(
        "cp.async.bulk.shared::cluster.global.mbarrier::complete_tx::bytes "
        "[%0], [%1], %2, [%3];"
        :: "r"(dst), "l"(src), "r"(bytes), "r"(mbar) : "memory");
}
#define MBAR_INIT(addr, cnt) \
    asm volatile("mbarrier.init.shared.b64 [%0], %1;" :: "r"(addr), "r"(cnt) : "memory")
#define MBAR_EXPECT_TX(addr, bytes) \
    asm volatile("mbarrier.arrive.expect_tx.shared.b64 _, [%0], %1;" \
                 :: "r"(addr), "r"(bytes) : "memory")
#define MBAR_WAIT(mbar, parity) do {                                        \
    asm volatile(                                                           \
        "{\n\t.reg .pred P1;\n\t"                                           \
        "WL_%=:\n\t"                                                        \
        "mbarrier.try_wait.parity.acquire.cta.shared::cta.b64 P1, [%0], %1, 0x989680;\n\t" \
        "@P1 bra.uni WD_%=;\n\t"                                            \
        "bra.uni WL_%=;\n\t"                                                \
        "WD_%=:\n\t}"                                                       \
        :: "r"(mbar), "r"(parity) : "memory");                              \
} while (0)

// ---------------- fp32 -> fp16 hi/lo split into tiled+swizzled layout -------
__device__ __forceinline__ unsigned pack2hi(float a, float b){
    __half2 t = __halves2half2(__float2half_rn(a), __float2half_rn(b));
    return *(unsigned*)&t;
}
__device__ __forceinline__ unsigned pack2lo(float a, float b){
    float ha = __half2float(__float2half_rn(a));
    float hb = __half2float(__float2half_rn(b));
    __half2 t = __halves2half2(__float2half_rn(a - ha), __float2half_rn(b - hb));
    return *(unsigned*)&t;
}

// A-type: 128-row tiles of 128B rows (64 halves), SW128 swizzled, 16KB/tile
__global__ void split_tiled_A(const float* __restrict__ src,
                              __half* __restrict__ hi,
                              __half* __restrict__ lo,
                              int Mvalid, int Mpad, int K)
{
    const int id = blockIdx.x * 256 + threadIdx.x;
    const int CK = K >> 3;
    if (id >= Mpad * CK) return;
    const int m = id / CK, c = id % CK;
    float4 x0 = make_float4(0.f,0.f,0.f,0.f), x1 = x0;
    if (m < Mvalid) {
        const float4* s = (const float4*)(src + (size_t)m * K + c * 8);
        x0 = s[0]; x1 = s[1];
    }
    const size_t tile = (size_t)(m >> 7) * (K >> 6) + (c >> 3);
    const unsigned inner = (unsigned)((m & 127) * 128 + (((c & 7) * 16) ^ ((m & 7) * 16)));
    uint4 h = make_uint4(pack2hi(x0.x,x0.y), pack2hi(x0.z,x0.w),
                         pack2hi(x1.x,x1.y), pack2hi(x1.z,x1.w));
    uint4 l = make_uint4(pack2lo(x0.x,x0.y), pack2lo(x0.z,x0.w),
                         pack2lo(x1.x,x1.y), pack2lo(x1.z,x1.w));
    *(uint4*)((char*)hi + tile * 16384 + inner) = h;
    *(uint4*)((char*)lo + tile * 16384 + inner) = l;
}

// B-type: 256-row tiles of 128B rows, SW128 swizzled, 32KB/tile
__global__ void split_tiled_B(const float* __restrict__ src,
                              __half* __restrict__ hi,
                              __half* __restrict__ lo,
                              int N, int K)
{
    const int id = blockIdx.x * 256 + threadIdx.x;
    const int CK = K >> 3;
    if (id >= N * CK) return;
    const int n = id / CK, c = id % CK;
    const float4* s = (const float4*)(src + (size_t)n * K + c * 8);
    float4 x0 = s[0], x1 = s[1];
    const size_t tile = (size_t)(n >> 8) * (K >> 6) + (c >> 3);
    const unsigned inner = (unsigned)((n & 255) * 128 + (((c & 7) * 16) ^ ((n & 7) * 16)));
    uint4 h = make_uint4(pack2hi(x0.x,x0.y), pack2hi(x0.z,x0.w),
                         pack2hi(x1.x,x1.y), pack2hi(x1.z,x1.w));
    uint4 l = make_uint4(pack2lo(x0.x,x0.y), pack2lo(x0.z,x0.w),
                         pack2lo(x1.x,x1.y), pack2lo(x1.z,x1.w));
    *(uint4*)((char*)hi + tile * 32768 + inner) = h;
    *(uint4*)((char*)lo + tile * 32768 + inner) = l;
}

__global__ void prep_scale_kernel(const float* __restrict__ pds, float* __restrict__ out)
{
    int d = threadIdx.x;
    if (d < D_) {
        float x = pds[d];
        float sp = (x > 20.f) ? x : log1pf(expf(x));
        out[d] = QSCALE_BASE * sp;
    }
}

// ============================================================================
// fp16 hi/lo tensor-core NT GEMM with cp.async.bulk tile loads.
// 128x256 CTA tile, 256 threads (8 warps 2x4), warp tile 64x64,
// BK=64 halves, 2-stage mbarrier pipeline, m16n8k16 f16.
// NPASS=3: Ah*Bh + Al*Bh + Ah*Bl.  NPASS=2: Ah*Bh + Al*Bh (=A*Bh).
// mode: 0 plain f32; 1 colscale f32; 2 const-scale f32; 3 plain f16 output.
// ============================================================================
#define TILEA_B  16384
#define TILEB_B  32768
#define STB_     (2*TILEA_B + 2*TILEB_B)   // 98304 per stage
#define SMEM_GEMM_ (2*STB_ + 128)          // 196736

#define SOFF_AH_ 0
#define SOFF_AL_ TILEA_B
#define SOFF_BH_ (2*TILEA_B)
#define SOFF_BL_ (2*TILEA_B + TILEB_B)

template<int NPASS>
__global__ void __launch_bounds__(256)
gemm_bulk(const __half* __restrict__ Aht, const __half* __restrict__ Alt,
          const __half* __restrict__ Bht, const __half* __restrict__ Blt,
          float* __restrict__ C, int M, int N, int K,
          int mode, const float* __restrict__ colscale, float cscale)
{
    extern __shared__ char smem[];
    const unsigned sb = (unsigned)__cvta_generic_to_shared(smem);
    const unsigned mb0 = sb + 2 * STB_;

    const int tid  = threadIdx.x;
    const int lane = tid & 31;
    const int warp = tid >> 5;
    const int wm = warp >> 2;
    const int wn = warp & 3;
    const int lr = lane >> 2;
    const int lc = lane & 3;

    const int KT = K >> 6;
    const int aTile = blockIdx.y * KT;
    const int bTile = blockIdx.x * KT;

    if (tid == 0) { MBAR_INIT(mb0, 1); MBAR_INIT(mb0 + 8, 1); }
    __syncthreads();

    float acc[4][8][4];
#pragma unroll
    for (int i = 0; i < 4; i++)
#pragma unroll
        for (int j = 0; j < 8; j++)
#pragma unroll
            for (int r = 0; r < 4; r++) acc[i][j][r] = 0.f;

    const int g  = lane >> 3;
    const int tr = lane & 7;
    unsigned aoff[4], aswz[4];
#pragma unroll
    for (int mt = 0; mt < 4; mt++) {
        const int row = wm * 64 + mt * 16 + (g & 1) * 8 + tr;
        aoff[mt] = (unsigned)(row * 128);
        aswz[mt] = (unsigned)((row & 7) * 16);
    }
    const unsigned alane = (unsigned)((g >> 1) * 16);
    unsigned boff[4], bswz[4];
#pragma unroll
    for (int n2 = 0; n2 < 4; n2++) {
        const int n = wn * 64 + n2 * 16 + (g >> 1) * 8 + tr;
        boff[n2] = (unsigned)(n * 128);
        bswz[n2] = (unsigned)((n & 7) * 16);
    }
    const unsigned blane = (unsigned)((g & 1) * 16);

    const unsigned stage_tx = (NPASS == 3) ? (unsigned)STB_ : (unsigned)(STB_ - TILEB_B);

    auto issue = [&](int it, int s){
        if (tid == 0) {
            const unsigned mb = mb0 + s * 8;
            MBAR_EXPECT_TX(mb, stage_tx);
            const unsigned dst = sb + s * STB_;
            bulk_cp(dst + SOFF_AH_, (const char*)Aht + (size_t)(aTile + it) * TILEA_B, TILEA_B, mb);
            bulk_cp(dst + SOFF_AL_, (const char*)Alt + (size_t)(aTile + it) * TILEA_B, TILEA_B, mb);
            bulk_cp(dst + SOFF_BH_, (const char*)Bht + (size_t)(bTile + it) * TILEB_B, TILEB_B, mb);
            if (NPASS == 3)
                bulk_cp(dst + SOFF_BL_, (const char*)Blt + (size_t)(bTile + it) * TILEB_B, TILEB_B, mb);
        }
    };

    issue(0, 0);
    issue(1, 1);

    for (int it = 0; it < KT; it++) {
        const int s = it & 1;
        MBAR_WAIT(mb0 + s * 8, (unsigned)((it >> 1) & 1));

        const unsigned base = sb + s * STB_;
        const unsigned sAh = base + SOFF_AH_;
        const unsigned sAl = base + SOFF_AL_;
        const unsigned sBh = base + SOFF_BH_;
        const unsigned sBl = base + SOFF_BL_;

#pragma unroll
        for (int k0 = 0; k0 < 4; k0++) {
            const unsigned kb = (unsigned)(k0 * 32);

            unsigned ah[4][4], bh[4][4];
#pragma unroll
            for (int mt = 0; mt < 4; mt++)
                ldsm4(ah[mt], sAh + aoff[mt] + ((kb + alane) ^ aswz[mt]));
#pragma unroll
            for (int n2 = 0; n2 < 4; n2++)
                ldsm4(bh[n2], sBh + boff[n2] + ((kb + blane) ^ bswz[n2]));
#pragma unroll
            for (int mt = 0; mt < 4; mt++)
#pragma unroll
                for (int nt = 0; nt < 8; nt++)
                    mma_f16(acc[mt][nt], ah[mt][0], ah[mt][1], ah[mt][2], ah[mt][3],
                            bh[nt >> 1][(nt & 1) * 2], bh[nt >> 1][(nt & 1) * 2 + 1]);

            unsigned xl[4][4];
#pragma unroll
            for (int mt = 0; mt < 4; mt++)
                ldsm4(xl[mt], sAl + aoff[mt] + ((kb + alane) ^ aswz[mt]));
#pragma unroll
            for (int mt = 0; mt < 4; mt++)
#pragma unroll
                for (int nt = 0; nt < 8; nt++)
                    mma_f16(acc[mt][nt], xl[mt][0], xl[mt][1], xl[mt][2], xl[mt][3],
                            bh[nt >> 1][(nt & 1) * 2], bh[nt >> 1][(nt & 1) * 2 + 1]);

            if (NPASS == 3) {
#pragma unroll
                for (int n2 = 0; n2 < 4; n2++)
                    ldsm4(xl[n2], sBl + boff[n2] + ((kb + blane) ^ bswz[n2]));
#pragma unroll
                for (int mt = 0; mt < 4; mt++)
#pragma unroll
                    for (int nt = 0; nt < 8; nt++)
                        mma_f16(acc[mt][nt], ah[mt][0], ah[mt][1], ah[mt][2], ah[mt][3],
                                xl[nt >> 1][(nt & 1) * 2], xl[nt >> 1][(nt & 1) * 2 + 1]);
            }
        }
        __syncthreads();
        if (it + 2 < KT) issue(it + 2, s);
    }

    // --- epilogue ---
    const int bm = blockIdx.y * 128;
    const int bn = blockIdx.x * 256;
#pragma unroll
    for (int mt = 0; mt < 4; mt++) {
#pragma unroll
        for (int nt = 0; nt < 8; nt++) {
            const int r0 = bm + wm * 64 + mt * 16 + lr;
            const int c0 = bn + wn * 64 + nt * 8 + 2 * lc;
            float v0 = acc[mt][nt][0], v1 = acc[mt][nt][1];
            float v2 = acc[mt][nt][2], v3 = acc[mt][nt][3];
            if (mode == 1) {
                const float s0 = colscale[c0 & (D_-1)], s1 = colscale[(c0+1) & (D_-1)];
                v0 *= s0; v1 *= s1; v2 *= s0; v3 *= s1;
            } else if (mode == 2) {
                v0 *= cscale; v1 *= cscale; v2 *= cscale; v3 *= cscale;
            }
            if (mode == 3) {
                __half* Ch = (__half*)C;
                if (r0 < M)
                    *(__half2*)(Ch + (size_t)r0 * N + c0) =
                        __halves2half2(__float2half_rn(v0), __float2half_rn(v1));
                if (r0 + 8 < M)
                    *(__half2*)(Ch + (size_t)(r0+8) * N + c0) =
                        __halves2half2(__float2half_rn(v2), __float2half_rn(v3));
            } else {
                if (r0 < M)     *(float2*)(C + (size_t)r0      * N + c0) = make_float2(v0, v1);
                if (r0 + 8 < M) *(float2*)(C + (size_t)(r0+8)  * N + c0) = make_float2(v2, v3);
            }
        }
    }
}

// ---------------- chunked local attention (fused hi/lo tiled output) --------
__global__ void __launch_bounds__(384)
attn_kernel(const float* __restrict__ q, const float* __restrict__ k,
            const __half* __restrict__ vh, const float* __restrict__ relk,
            __half* __restrict__ och, __half* __restrict__ ocl,
            float* __restrict__ attn_out)
{
    __shared__ float sq[CHUNK_][129];
    __shared__ float sk[CTX_][129];
    __shared__ float sv[CTX_][129];
    __shared__ float sr[CTX_][129];
    __shared__ float sac[CHUNK_][CTX_];
    __shared__ float sbd[CHUNK_][CTX_];
    __shared__ float sw[CHUNK_][25];

    const int n = blockIdx.x, h = blockIdx.y, b = blockIdx.z;
    const int t = threadIdx.x;

    for (int i = t; i < CHUNK_ * D_; i += 384) {
        const int c = i >> 7, d = i & 127;
        const int s = n * CHUNK_ + c;
        sq[c][d] = q[((size_t)(b * S_ + s)) * E_ + h * D_ + d];
    }
    for (int i = t; i < CTX_ * D_; i += 384) {
        const int j = i >> 7, d = i & 127;
        const int s = n * CHUNK_ - 12 + j;
        float kv = 0.f, vv = 0.f;
        if (s >= 0 && s < S_) {
            const size_t base = ((size_t)(b * S_ + s)) * E_ + h * D_ + d;
            kv = k[base];
            vv = __half2float(vh[base]);
        }
        sk[j][d] = kv;
        sv[j][d] = vv;
        sr[j][d] = relk[(size_t)j * E_ + h * D_ + d];
    }
    __syncthreads();

    for (int i = t; i < CHUNK_ * CTX_; i += 384) {
        const int c = i / CTX_, j = i % CTX_;
        float a = 0.f, bb = 0.f;
#pragma unroll 8
        for (int d = 0; d < D_; d++) {
            const float qq = sq[c][d];
            a  = fmaf(qq, sk[j][d], a);
            bb = fmaf(qq, sr[j][d], bb);
        }
        sac[c][j] = a;
        sbd[c][j] = bb;
    }
    __syncthreads();

    for (int i = t; i < CHUNK_ * CTX_; i += 384) {
        const int c = i / CTX_, j = i % CTX_;
        const int idx = c * CTX_ + j;
        const int r = idx / (CTX_ + 1);
        const int p = idx % (CTX_ + 1);
        const float bd = (p < CTX_) ? sbd[r][p] : 0.f;
        float l = sac[c][j] + bd;
        l = 50.f * tanhf(l * 0.02f);
        sw[c][j] = l;
    }
    __syncthreads();

    if (t < CHUNK_) {
        const int c = t;
        float m = -1e30f;
        for (int j = 0; j < CTX_; j++) m = fmaxf(m, sw[c][j]);
        float sum = 0.f;
        for (int j = 0; j < CTX_; j++) { const float e = expf(sw[c][j] - m); sum += e; sw[c][j] = e; }
        const float inv = 1.f / sum;
        for (int j = 0; j < CTX_; j++) sw[c][j] *= inv;
    }
    __syncthreads();

    if (attn_out) {
        for (int i = t; i < CHUNK_ * CTX_; i += 384) {
            const int c = i / CTX_, j = i % CTX_;
            attn_out[((((size_t)b * H_ + h) * NB_ + n) * CHUNK_ + c) * CTX_ + j] = sw[c][j];
        }
    }

    // out[c][d] -> fp16 hi/lo, written directly in the A-tile swizzled layout
    for (int i = t; i < CHUNK_ * (D_ / 2); i += 384) {
        const int c = i >> 6, d2 = (i & 63) * 2;
        float a0 = 0.f, a1 = 0.f;
#pragma unroll
        for (int j = 0; j < CTX_; j++) {
            const float w = sw[c][j];
            a0 = fmaf(w, sv[j][d2],     a0);
            a1 = fmaf(w, sv[j][d2 + 1], a1);
        }
        const int m = b * S_ + n * CHUNK_ + c;
        const int e = h * D_ + d2;
        const int ch = e >> 3;
        const size_t tile = (size_t)(m >> 7) * (E_ >> 6) + (ch >> 3);
        const unsigned inner = (unsigned)((m & 127) * 128 +
                               (((ch & 7) * 16) ^ ((m & 7) * 16)) + (e & 7) * 2);
        const __half h0 = __float2half_rn(a0), h1 = __float2half_rn(a1);
        *(__half2*)((char*)och + tile * 16384 + inner) = __halves2half2(h0, h1);
        *(__half2*)((char*)ocl + tile * 16384 + inner) =
            __halves2half2(__float2half_rn(a0 - __half2float(h0)),
                           __float2half_rn(a1 - __half2float(h1)));
    }
}

// ---------------- launch -----------------------------------------------------
extern "C" void kernel_launch(void* const* d_in, const int* in_sizes, int n_in,
                              void* d_out, int out_size)
{
    const float* hs   = (const float*)d_in[0];
    const float* pe   = (const float*)d_in[1];
    const float* w_q  = (const float*)d_in[2];
    const float* w_k  = (const float*)d_in[3];
    const float* w_v  = (const float*)d_in[4];
    const float* w_p  = (const float*)d_in[5];
    const float* w_r  = (const float*)d_in[6];
    const float* pds  = (const float*)d_in[7];
    float* out = (float*)d_out;

    float *q, *k, *rk, *qs;
    __half *vh;
    cudaGetSymbolAddress((void**)&q,  g_q);
    cudaGetSymbolAddress((void**)&k,  g_k);
    cudaGetSymbolAddress((void**)&vh, g_vh);
    cudaGetSymbolAddress((void**)&rk, g_relk);
    cudaGetSymbolAddress((void**)&qs, g_qdscale);

    __half *hsh, *hsl, *och, *ocl, *wh, *wl, *peh, *pel;
    cudaGetSymbolAddress((void**)&hsh, g_hs_hi);
    cudaGetSymbolAddress((void**)&hsl, g_hs_lo);
    cudaGetSymbolAddress((void**)&och, g_oc_hi);
    cudaGetSymbolAddress((void**)&ocl, g_oc_lo);
    cudaGetSymbolAddress((void**)&wh,  g_w_hi);
    cudaGetSymbolAddress((void**)&wl,  g_w_lo);
    cudaGetSymbolAddress((void**)&peh, g_pe_hi);
    cudaGetSymbolAddress((void**)&pel, g_pe_lo);

    cudaFuncSetAttribute(gemm_bulk<3>, cudaFuncAttributeMaxDynamicSharedMemorySize, SMEM_GEMM_);
    cudaFuncSetAttribute(gemm_bulk<2>, cudaFuncAttributeMaxDynamicSharedMemorySize, SMEM_GEMM_);

    prep_scale_kernel<<<1, 128>>>(pds, qs);

    const int tA = MTOK_ * (E_ / 8);
    split_tiled_A<<<(tA + 255) / 256, 256>>>(hs, hsh, hsl, MTOK_, MTOK_, E_);
    const int tB = E_ * (E_ / 8);
    split_tiled_B<<<(tB + 255) / 256, 256>>>(w_q, wh + 0*(size_t)WELEM_, wl + 0*(size_t)WELEM_, E_, E_);
    split_tiled_B<<<(tB + 255) / 256, 256>>>(w_k, wh + 1*(size_t)WELEM_, wl + 1*(size_t)WELEM_, E_, E_);
    split_tiled_B<<<(tB + 255) / 256, 256>>>(w_v, wh + 2*(size_t)WELEM_, wl + 2*(size_t)WELEM_, E_, E_);
    split_tiled_B<<<(tB + 255) / 256, 256>>>(w_p, wh + 3*(size_t)WELEM_, wl + 3*(size_t)WELEM_, E_, E_);
    split_tiled_B<<<(tB + 255) / 256, 256>>>(w_r, wh + 4*(size_t)WELEM_, wl + 4*(size_t)WELEM_, E_, E_);
    const int tPE = 128 * (E_ / 8);
    split_tiled_A<<<(tPE + 255) / 256, 256>>>(pe, peh, pel, CTX_, 128, E_);

    const dim3 gBig(E_ / 256, MTOK_ / 128);   // (6, 192)
    gemm_bulk<3><<<gBig, 256, SMEM_GEMM_>>>(hsh, hsl, wh + 0*(size_t)WELEM_, wl + 0*(size_t)WELEM_,
                                            q, MTOK_, E_, E_, 1, qs, 1.f);
    gemm_bulk<3><<<gBig, 256, SMEM_GEMM_>>>(hsh, hsl, wh + 1*(size_t)WELEM_, wl + 1*(size_t)WELEM_,
                                            k, MTOK_, E_, E_, 2, nullptr, KSCALE);
    gemm_bulk<2><<<gBig, 256, SMEM_GEMM_>>>(hsh, hsl, wh + 2*(size_t)WELEM_, wl + 2*(size_t)WELEM_,
                                            (float*)vh, MTOK_, E_, E_, 3, nullptr, 1.f);
    gemm_bulk<3><<<dim3(E_ / 256, 1), 256, SMEM_GEMM_>>>(peh, pel, wh + 4*(size_t)WELEM_, wl + 4*(size_t)WELEM_,
                                            rk, CTX_, E_, E_, 0, nullptr, 1.f);

    float* attn = ((size_t)out_size >= OUT_MAIN + ATTN_SZ) ? (out + OUT_MAIN) : nullptr;
    attn_kernel<<<dim3(NB_, H_, B_), 384>>>(q, k, vh, rk, och, ocl, attn);

    gemm_bulk<2><<<gBig, 256, SMEM_GEMM_>>>(och, ocl, wh + 3*(size_t)WELEM_, wl + 3*(size_t)WELEM_,
                                            out, MTOK_, E_, E_, 0, nullptr, 1.f);
}

// round 12
// speedup vs baseline: 1.0447x; 1.0447x over previous
#include <cuda_runtime.h>
#include <cuda_fp16.h>
#include <stdint.h>
#include <math.h>

// ---------------- problem constants ----------------
#define B_    8
#define S_    3072
#define H_    12
#define D_    128
#define E_    1536
#define NB_   256
#define CHUNK_ 12
#define CTX_  24
#define MTOK_ (B_*S_)         // 24576

#define OUT_MAIN  ((size_t)MTOK_ * E_)
#define ATTN_SZ   ((size_t)B_*H_*NB_*CHUNK_*CTX_)
#define WELEM_    (E_*E_)

#define QSCALE_BASE (0.088388347648318447f / 0.69314718055994531f)
#define KSCALE      (1.3132616875182228f  / 0.69314718055994531f)

// ---------------- scratch (device globals) ----------------
__device__ float g_q[OUT_MAIN];
__device__ float g_k[OUT_MAIN];
__device__ __half g_vh[OUT_MAIN];          // v projection in fp16
__device__ float g_relk[CTX_ * E_];
__device__ float g_qdscale[D_];

// tiled+swizzled fp16 hi/lo operand storage
__device__ __half g_hs_hi[OUT_MAIN];
__device__ __half g_hs_lo[OUT_MAIN];
__device__ __half g_oc_hi[OUT_MAIN];       // attention output, tiled+swizzled
__device__ __half g_oc_lo[OUT_MAIN];
__device__ __half g_w_hi[5][WELEM_];
__device__ __half g_w_lo[5][WELEM_];
__device__ __half g_pe_hi[128 * E_];
__device__ __half g_pe_lo[128 * E_];

// ---------------- helpers ----------------
__device__ __forceinline__ void mma_f16(float c[4], unsigned a0, unsigned a1,
                                        unsigned a2, unsigned a3,
                                        unsigned b0, unsigned b1){
    asm volatile(
        "mma.sync.aligned.m16n8k16.row.col.f32.f16.f16.f32 "
        "{%0,%1,%2,%3}, {%4,%5,%6,%7}, {%8,%9}, {%0,%1,%2,%3};"
        : "+f"(c[0]), "+f"(c[1]), "+f"(c[2]), "+f"(c[3])
        : "r"(a0), "r"(a1), "r"(a2), "r"(a3), "r"(b0), "r"(b1));
}
__device__ __forceinline__ void ldsm4(unsigned r[4], unsigned addr){
    asm volatile("ldmatrix.sync.aligned.m8n8.x4.shared.b16 {%0,%1,%2,%3}, [%4];"
                 : "=r"(r[0]), "=r"(r[1]), "=r"(r[2]), "=r"(r[3]) : "r"(addr));
}
__device__ __forceinline__ void bulk_cp(unsigned dst, const void* src, unsigned bytes,
                                        unsigned mbar){
    asm volatile(
        "cp.async.bulk.shared::cluster.global.mbarrier::complete_tx::bytes "
        "[%0], [%1], %2, [%3];"
        :: "r"(dst), "l"(src), "r"(bytes), "r"(mbar) : "memory");
}
#define MBAR_INIT(addr, cnt) \
    asm volatile("mbarrier.init.shared.b64 [%0], %1;" :: "r"(addr), "r"(cnt) : "memory")
#define MBAR_EXPECT_TX(addr, bytes) \
    asm volatile("mbarrier.arrive.expect_tx.shared.b64 _, [%0], %1;" \
                 :: "r"(addr), "r"(bytes) : "memory")
#define MBAR_WAIT(mbar, parity) do {                                        \
    asm volatile(                                                           \
        "{\n\t.reg .pred P1;\n\t"                                           \
        "WL_%=:\n\t"                                                        \
        "mbarrier.try_wait.parity.acquire.cta.shared::cta.b64 P1, [%0], %1, 0x989680;\n\t" \
        "@P1 bra.uni WD_%=;\n\t"                                            \
        "bra.uni WL_%=;\n\t"                                                \
        "WD_%=:\n\t}"                                                       \
        :: "r"(mbar), "r"(parity) : "memory");                              \
} while (0)

// ---------------- fp32 -> fp16 hi/lo split into tiled+swizzled layout -------
__device__ __forceinline__ unsigned pack2hi(float a, float b){
    __half2 t = __halves2half2(__float2half_rn(a), __float2half_rn(b));
    return *(unsigned*)&t;
}
__device__ __forceinline__ unsigned pack2lo(float a, float b){
    float ha = __half2float(__float2half_rn(a));
    float hb = __half2float(__float2half_rn(b));
    __half2 t = __halves2half2(__float2half_rn(a - ha), __float2half_rn(b - hb));
    return *(unsigned*)&t;
}

// A-type: 128-row tiles of 128B rows (64 halves), SW128 swizzled, 16KB/tile
__global__ void split_tiled_A(const float* __restrict__ src,
                              __half* __restrict__ hi,
                              __half* __restrict__ lo,
                              int Mvalid, int Mpad, int K)
{
    const int id = blockIdx.x * 256 + threadIdx.x;
    const int CK = K >> 3;
    if (id >= Mpad * CK) return;
    const int m = id / CK, c = id % CK;
    float4 x0 = make_float4(0.f,0.f,0.f,0.f), x1 = x0;
    if (m < Mvalid) {
        const float4* s = (const float4*)(src + (size_t)m * K + c * 8);
        x0 = s[0]; x1 = s[1];
    }
    const size_t tile = (size_t)(m >> 7) * (K >> 6) + (c >> 3);
    const unsigned inner = (unsigned)((m & 127) * 128 + (((c & 7) * 16) ^ ((m & 7) * 16)));
    uint4 h = make_uint4(pack2hi(x0.x,x0.y), pack2hi(x0.z,x0.w),
                         pack2hi(x1.x,x1.y), pack2hi(x1.z,x1.w));
    uint4 l = make_uint4(pack2lo(x0.x,x0.y), pack2lo(x0.z,x0.w),
                         pack2lo(x1.x,x1.y), pack2lo(x1.z,x1.w));
    *(uint4*)((char*)hi + tile * 16384 + inner) = h;
    *(uint4*)((char*)lo + tile * 16384 + inner) = l;
}

// B-type: 256-row tiles of 128B rows, SW128 swizzled, 32KB/tile
__global__ void split_tiled_B(const float* __restrict__ src,
                              __half* __restrict__ hi,
                              __half* __restrict__ lo,
                              int N, int K)
{
    const int id = blockIdx.x * 256 + threadIdx.x;
    const int CK = K >> 3;
    if (id >= N * CK) return;
    const int n = id / CK, c = id % CK;
    const float4* s = (const float4*)(src + (size_t)n * K + c * 8);
    float4 x0 = s[0], x1 = s[1];
    const size_t tile = (size_t)(n >> 8) * (K >> 6) + (c >> 3);
    const unsigned inner = (unsigned)((n & 255) * 128 + (((c & 7) * 16) ^ ((n & 7) * 16)));
    uint4 h = make_uint4(pack2hi(x0.x,x0.y), pack2hi(x0.z,x0.w),
                         pack2hi(x1.x,x1.y), pack2hi(x1.z,x1.w));
    uint4 l = make_uint4(pack2lo(x0.x,x0.y), pack2lo(x0.z,x0.w),
                         pack2lo(x1.x,x1.y), pack2lo(x1.z,x1.w));
    *(uint4*)((char*)hi + tile * 32768 + inner) = h;
    *(uint4*)((char*)lo + tile * 32768 + inner) = l;
}

__global__ void prep_scale_kernel(const float* __restrict__ pds, float* __restrict__ out)
{
    int d = threadIdx.x;
    if (d < D_) {
        float x = pds[d];
        float sp = (x > 20.f) ? x : log1pf(expf(x));
        out[d] = QSCALE_BASE * sp;
    }
}

// ============================================================================
// fp16 hi/lo tensor-core NT GEMM with cp.async.bulk tile loads.
// 128x256 CTA tile, 256 threads (8 warps 2x4), warp tile 64x64,
// BK=64 halves, 2-stage mbarrier pipeline, m16n8k16 f16.
// NPASS=3: Ah*Bh + Al*Bh + Ah*Bl.  NPASS=2: Ah*Bh + Al*Bh (=A*Bh).
// mode: 0 plain f32; 1 colscale f32; 2 const-scale f32; 3 plain f16 output.
// ============================================================================
#define TILEA_B  16384
#define TILEB_B  32768
#define STB_     (2*TILEA_B + 2*TILEB_B)   // 98304 per stage
#define SMEM_GEMM_ (2*STB_ + 128)          // 196736

#define SOFF_AH_ 0
#define SOFF_AL_ TILEA_B
#define SOFF_BH_ (2*TILEA_B)
#define SOFF_BL_ (2*TILEA_B + TILEB_B)

template<int NPASS>
__global__ void __launch_bounds__(256)
gemm_bulk(const __half* __restrict__ Aht, const __half* __restrict__ Alt,
          const __half* __restrict__ Bht, const __half* __restrict__ Blt,
          float* __restrict__ C, int M, int N, int K,
          int mode, const float* __restrict__ colscale, float cscale)
{
    extern __shared__ char smem[];
    const unsigned sb = (unsigned)__cvta_generic_to_shared(smem);
    const unsigned mb0 = sb + 2 * STB_;

    const int tid  = threadIdx.x;
    const int lane = tid & 31;
    const int warp = tid >> 5;
    const int wm = warp >> 2;
    const int wn = warp & 3;
    const int lr = lane >> 2;
    const int lc = lane & 3;

    const int KT = K >> 6;
    const int aTile = blockIdx.y * KT;
    const int bTile = blockIdx.x * KT;

    if (tid == 0) { MBAR_INIT(mb0, 1); MBAR_INIT(mb0 + 8, 1); }
    __syncthreads();

    float acc[4][8][4];
#pragma unroll
    for (int i = 0; i < 4; i++)
#pragma unroll
        for (int j = 0; j < 8; j++)
#pragma unroll
            for (int r = 0; r < 4; r++) acc[i][j][r] = 0.f;

    const int g  = lane >> 3;
    const int tr = lane & 7;
    unsigned aoff[4], aswz[4];
#pragma unroll
    for (int mt = 0; mt < 4; mt++) {
        const int row = wm * 64 + mt * 16 + (g & 1) * 8 + tr;
        aoff[mt] = (unsigned)(row * 128);
        aswz[mt] = (unsigned)((row & 7) * 16);
    }
    const unsigned alane = (unsigned)((g >> 1) * 16);
    unsigned boff[4], bswz[4];
#pragma unroll
    for (int n2 = 0; n2 < 4; n2++) {
        const int n = wn * 64 + n2 * 16 + (g >> 1) * 8 + tr;
        boff[n2] = (unsigned)(n * 128);
        bswz[n2] = (unsigned)((n & 7) * 16);
    }
    const unsigned blane = (unsigned)((g & 1) * 16);

    const unsigned stage_tx = (NPASS == 3) ? (unsigned)STB_ : (unsigned)(STB_ - TILEB_B);

    auto issue = [&](int it, int s){
        if (tid == 0) {
            const unsigned mb = mb0 + s * 8;
            MBAR_EXPECT_TX(mb, stage_tx);
            const unsigned dst = sb + s * STB_;
            bulk_cp(dst + SOFF_AH_, (const char*)Aht + (size_t)(aTile + it) * TILEA_B, TILEA_B, mb);
            bulk_cp(dst + SOFF_AL_, (const char*)Alt + (size_t)(aTile + it) * TILEA_B, TILEA_B, mb);
            bulk_cp(dst + SOFF_BH_, (const char*)Bht + (size_t)(bTile + it) * TILEB_B, TILEB_B, mb);
            if (NPASS == 3)
                bulk_cp(dst + SOFF_BL_, (const char*)Blt + (size_t)(bTile + it) * TILEB_B, TILEB_B, mb);
        }
    };

    issue(0, 0);
    issue(1, 1);

    for (int it = 0; it < KT; it++) {
        const int s = it & 1;
        MBAR_WAIT(mb0 + s * 8, (unsigned)((it >> 1) & 1));

        const unsigned base = sb + s * STB_;
        const unsigned sAh = base + SOFF_AH_;
        const unsigned sAl = base + SOFF_AL_;
        const unsigned sBh = base + SOFF_BH_;
        const unsigned sBl = base + SOFF_BL_;

#pragma unroll
        for (int k0 = 0; k0 < 4; k0++) {
            const unsigned kb = (unsigned)(k0 * 32);

            unsigned ah[4][4], bh[4][4];
#pragma unroll
            for (int mt = 0; mt < 4; mt++)
                ldsm4(ah[mt], sAh + aoff[mt] + ((kb + alane) ^ aswz[mt]));
#pragma unroll
            for (int n2 = 0; n2 < 4; n2++)
                ldsm4(bh[n2], sBh + boff[n2] + ((kb + blane) ^ bswz[n2]));
#pragma unroll
            for (int mt = 0; mt < 4; mt++)
#pragma unroll
                for (int nt = 0; nt < 8; nt++)
                    mma_f16(acc[mt][nt], ah[mt][0], ah[mt][1], ah[mt][2], ah[mt][3],
                            bh[nt >> 1][(nt & 1) * 2], bh[nt >> 1][(nt & 1) * 2 + 1]);

            unsigned xl[4][4];
#pragma unroll
            for (int mt = 0; mt < 4; mt++)
                ldsm4(xl[mt], sAl + aoff[mt] + ((kb + alane) ^ aswz[mt]));
#pragma unroll
            for (int mt = 0; mt < 4; mt++)
#pragma unroll
                for (int nt = 0; nt < 8; nt++)
                    mma_f16(acc[mt][nt], xl[mt][0], xl[mt][1], xl[mt][2], xl[mt][3],
                            bh[nt >> 1][(nt & 1) * 2], bh[nt >> 1][(nt & 1) * 2 + 1]);

            if (NPASS == 3) {
#pragma unroll
                for (int n2 = 0; n2 < 4; n2++)
                    ldsm4(xl[n2], sBl + boff[n2] + ((kb + blane) ^ bswz[n2]));
#pragma unroll
                for (int mt = 0; mt < 4; mt++)
#pragma unroll
                    for (int nt = 0; nt < 8; nt++)
                        mma_f16(acc[mt][nt], ah[mt][0], ah[mt][1], ah[mt][2], ah[mt][3],
                                xl[nt >> 1][(nt & 1) * 2], xl[nt >> 1][(nt & 1) * 2 + 1]);
            }
        }
        __syncthreads();
        if (it + 2 < KT) issue(it + 2, s);
    }

    // --- epilogue ---
    const int bm = blockIdx.y * 128;
    const int bn = blockIdx.x * 256;
#pragma unroll
    for (int mt = 0; mt < 4; mt++) {
#pragma unroll
        for (int nt = 0; nt < 8; nt++) {
            const int r0 = bm + wm * 64 + mt * 16 + lr;
            const int c0 = bn + wn * 64 + nt * 8 + 2 * lc;
            float v0 = acc[mt][nt][0], v1 = acc[mt][nt][1];
            float v2 = acc[mt][nt][2], v3 = acc[mt][nt][3];
            if (mode == 1) {
                const float s0 = colscale[c0 & (D_-1)], s1 = colscale[(c0+1) & (D_-1)];
                v0 *= s0; v1 *= s1; v2 *= s0; v3 *= s1;
            } else if (mode == 2) {
                v0 *= cscale; v1 *= cscale; v2 *= cscale; v3 *= cscale;
            }
            if (mode == 3) {
                __half* Ch = (__half*)C;
                if (r0 < M)
                    *(__half2*)(Ch + (size_t)r0 * N + c0) =
                        __halves2half2(__float2half_rn(v0), __float2half_rn(v1));
                if (r0 + 8 < M)
                    *(__half2*)(Ch + (size_t)(r0+8) * N + c0) =
                        __halves2half2(__float2half_rn(v2), __float2half_rn(v3));
            } else {
                if (r0 < M)     *(float2*)(C + (size_t)r0      * N + c0) = make_float2(v0, v1);
                if (r0 + 8 < M) *(float2*)(C + (size_t)(r0+8)  * N + c0) = make_float2(v2, v3);
            }
        }
    }
}

// ---------------- chunked local attention (fused hi/lo tiled output) --------
// Output writes are 16B-vectorized: each task owns one 8-half chunk.
__global__ void __launch_bounds__(384)
attn_kernel(const float* __restrict__ q, const float* __restrict__ k,
            const __half* __restrict__ vh, const float* __restrict__ relk,
            __half* __restrict__ och, __half* __restrict__ ocl,
            float* __restrict__ attn_out)
{
    __shared__ float sq[CHUNK_][129];
    __shared__ float sk[CTX_][129];
    __shared__ float sv[CTX_][129];
    __shared__ float sr[CTX_][129];
    __shared__ float sac[CHUNK_][CTX_];
    __shared__ float sbd[CHUNK_][CTX_];
    __shared__ float sw[CHUNK_][25];

    const int n = blockIdx.x, h = blockIdx.y, b = blockIdx.z;
    const int t = threadIdx.x;

    for (int i = t; i < CHUNK_ * D_; i += 384) {
        const int c = i >> 7, d = i & 127;
        const int s = n * CHUNK_ + c;
        sq[c][d] = q[((size_t)(b * S_ + s)) * E_ + h * D_ + d];
    }
    for (int i = t; i < CTX_ * D_; i += 384) {
        const int j = i >> 7, d = i & 127;
        const int s = n * CHUNK_ - 12 + j;
        float kv = 0.f, vv = 0.f;
        if (s >= 0 && s < S_) {
            const size_t base = ((size_t)(b * S_ + s)) * E_ + h * D_ + d;
            kv = k[base];
            vv = __half2float(vh[base]);
        }
        sk[j][d] = kv;
        sv[j][d] = vv;
        sr[j][d] = relk[(size_t)j * E_ + h * D_ + d];
    }
    __syncthreads();

    for (int i = t; i < CHUNK_ * CTX_; i += 384) {
        const int c = i / CTX_, j = i % CTX_;
        float a = 0.f, bb = 0.f;
#pragma unroll 8
        for (int d = 0; d < D_; d++) {
            const float qq = sq[c][d];
            a  = fmaf(qq, sk[j][d], a);
            bb = fmaf(qq, sr[j][d], bb);
        }
        sac[c][j] = a;
        sbd[c][j] = bb;
    }
    __syncthreads();

    for (int i = t; i < CHUNK_ * CTX_; i += 384) {
        const int c = i / CTX_, j = i % CTX_;
        const int idx = c * CTX_ + j;
        const int r = idx / (CTX_ + 1);
        const int p = idx % (CTX_ + 1);
        const float bd = (p < CTX_) ? sbd[r][p] : 0.f;
        float l = sac[c][j] + bd;
        l = 50.f * tanhf(l * 0.02f);
        sw[c][j] = l;
    }
    __syncthreads();

    if (t < CHUNK_) {
        const int c = t;
        float m = -1e30f;
        for (int j = 0; j < CTX_; j++) m = fmaxf(m, sw[c][j]);
        float sum = 0.f;
        for (int j = 0; j < CTX_; j++) { const float e = expf(sw[c][j] - m); sum += e; sw[c][j] = e; }
        const float inv = 1.f / sum;
        for (int j = 0; j < CTX_; j++) sw[c][j] *= inv;
    }
    __syncthreads();

    if (attn_out) {
        for (int i = t; i < CHUNK_ * CTX_; i += 384) {
            const int c = i / CTX_, j = i % CTX_;
            attn_out[((((size_t)b * H_ + h) * NB_ + n) * CHUNK_ + c) * CTX_ + j] = sw[c][j];
        }
    }

    // out[c][d] -> fp16 hi/lo in A-tile swizzled layout, one 16B chunk/task
    for (int i = t; i < CHUNK_ * 16; i += 384) {        // 192 chunk-tasks
        const int c  = i >> 4;          // chunk row 0..11
        const int ci = i & 15;          // 8-half chunk within head 0..15
        const int d0 = ci * 8;
        float a[8];
#pragma unroll
        for (int x = 0; x < 8; x++) a[x] = 0.f;
#pragma unroll
        for (int j = 0; j < CTX_; j++) {
            const float w = sw[c][j];
#pragma unroll
            for (int x = 0; x < 8; x++) a[x] = fmaf(w, sv[j][d0 + x], a[x]);
        }
        const int m  = b * S_ + n * CHUNK_ + c;
        const int ch = h * 16 + ci;     // 8-half chunk within the E-row
        const size_t tile = (size_t)(m >> 7) * (E_ >> 6) + (ch >> 3);
        const unsigned inner = (unsigned)((m & 127) * 128 +
                               (((ch & 7) * 16) ^ ((m & 7) * 16)));
        uint4 hv = make_uint4(pack2hi(a[0],a[1]), pack2hi(a[2],a[3]),
                              pack2hi(a[4],a[5]), pack2hi(a[6],a[7]));
        uint4 lv = make_uint4(pack2lo(a[0],a[1]), pack2lo(a[2],a[3]),
                              pack2lo(a[4],a[5]), pack2lo(a[6],a[7]));
        *(uint4*)((char*)och + tile * 16384 + inner) = hv;
        *(uint4*)((char*)ocl + tile * 16384 + inner) = lv;
    }
}

// ---------------- launch -----------------------------------------------------
extern "C" void kernel_launch(void* const* d_in, const int* in_sizes, int n_in,
                              void* d_out, int out_size)
{
    const float* hs   = (const float*)d_in[0];
    const float* pe   = (const float*)d_in[1];
    const float* w_q  = (const float*)d_in[2];
    const float* w_k  = (const float*)d_in[3];
    const float* w_v  = (const float*)d_in[4];
    const float* w_p  = (const float*)d_in[5];
    const float* w_r  = (const float*)d_in[6];
    const float* pds  = (const float*)d_in[7];
    float* out = (float*)d_out;

    float *q, *k, *rk, *qs;
    __half *vh;
    cudaGetSymbolAddress((void**)&q,  g_q);
    cudaGetSymbolAddress((void**)&k,  g_k);
    cudaGetSymbolAddress((void**)&vh, g_vh);
    cudaGetSymbolAddress((void**)&rk, g_relk);
    cudaGetSymbolAddress((void**)&qs, g_qdscale);

    __half *hsh, *hsl, *och, *ocl, *wh, *wl, *peh, *pel;
    cudaGetSymbolAddress((void**)&hsh, g_hs_hi);
    cudaGetSymbolAddress((void**)&hsl, g_hs_lo);
    cudaGetSymbolAddress((void**)&och, g_oc_hi);
    cudaGetSymbolAddress((void**)&ocl, g_oc_lo);
    cudaGetSymbolAddress((void**)&wh,  g_w_hi);
    cudaGetSymbolAddress((void**)&wl,  g_w_lo);
    cudaGetSymbolAddress((void**)&peh, g_pe_hi);
    cudaGetSymbolAddress((void**)&pel, g_pe_lo);

    cudaFuncSetAttribute(gemm_bulk<3>, cudaFuncAttributeMaxDynamicSharedMemorySize, SMEM_GEMM_);
    cudaFuncSetAttribute(gemm_bulk<2>, cudaFuncAttributeMaxDynamicSharedMemorySize, SMEM_GEMM_);

    prep_scale_kernel<<<1, 128>>>(pds, qs);

    const int tA = MTOK_ * (E_ / 8);
    split_tiled_A<<<(tA + 255) / 256, 256>>>(hs, hsh, hsl, MTOK_, MTOK_, E_);
    const int tB = E_ * (E_ / 8);
    split_tiled_B<<<(tB + 255) / 256, 256>>>(w_q, wh + 0*(size_t)WELEM_, wl + 0*(size_t)WELEM_, E_, E_);
    split_tiled_B<<<(tB + 255) / 256, 256>>>(w_k, wh + 1*(size_t)WELEM_, wl + 1*(size_t)WELEM_, E_, E_);
    split_tiled_B<<<(tB + 255) / 256, 256>>>(w_v, wh + 2*(size_t)WELEM_, wl + 2*(size_t)WELEM_, E_, E_);
    split_tiled_B<<<(tB + 255) / 256, 256>>>(w_p, wh + 3*(size_t)WELEM_, wl + 3*(size_t)WELEM_, E_, E_);
    split_tiled_B<<<(tB + 255) / 256, 256>>>(w_r, wh + 4*(size_t)WELEM_, wl + 4*(size_t)WELEM_, E_, E_);
    const int tPE = 128 * (E_ / 8);
    split_tiled_A<<<(tPE + 255) / 256, 256>>>(pe, peh, pel, CTX_, 128, E_);

    const dim3 gBig(E_ / 256, MTOK_ / 128);   // (6, 192)
    gemm_bulk<3><<<gBig, 256, SMEM_GEMM_>>>(hsh, hsl, wh + 0*(size_t)WELEM_, wl + 0*(size_t)WELEM_,
                                            q, MTOK_, E_, E_, 1, qs, 1.f);
    gemm_bulk<3><<<gBig, 256, SMEM_GEMM_>>>(hsh, hsl, wh + 1*(size_t)WELEM_, wl + 1*(size_t)WELEM_,
                                            k, MTOK_, E_, E_, 2, nullptr, KSCALE);
    gemm_bulk<2><<<gBig, 256, SMEM_GEMM_>>>(hsh, hsl, wh + 2*(size_t)WELEM_, wl + 2*(size_t)WELEM_,
                                            (float*)vh, MTOK_, E_, E_, 3, nullptr, 1.f);
    gemm_bulk<3><<<dim3(E_ / 256, 1), 256, SMEM_GEMM_>>>(peh, pel, wh + 4*(size_t)WELEM_, wl + 4*(size_t)WELEM_,
                                            rk, CTX_, E_, E_, 0, nullptr, 1.f);

    float* attn = ((size_t)out_size >= OUT_MAIN + ATTN_SZ) ? (out + OUT_MAIN) : nullptr;
    attn_kernel<<<dim3(NB_, H_, B_), 384>>>(q, k, vh, rk, och, ocl, attn);

    gemm_bulk<2><<<gBig, 256, SMEM_GEMM_>>>(och, ocl, wh + 3*(size_t)WELEM_, wl + 3*(size_t)WELEM_,
                                            out, MTOK_, E_, E_, 0, nullptr, 1.f);
}

// round 13
// speedup vs baseline: 1.0556x; 1.0105x over previous
#include <cuda_runtime.h>
#include <cuda_fp16.h>
#include <stdint.h>
#include <math.h>

// ---------------- problem constants ----------------
#define B_    8
#define S_    3072
#define H_    12
#define D_    128
#define E_    1536
#define NB_   256
#define CHUNK_ 12
#define CTX_  24
#define MTOK_ (B_*S_)         // 24576

#define OUT_MAIN  ((size_t)MTOK_ * E_)
#define ATTN_SZ   ((size_t)B_*H_*NB_*CHUNK_*CTX_)
#define WELEM_    (E_*E_)

#define QSCALE_BASE (0.088388347648318447f / 0.69314718055994531f)
#define KSCALE      (1.3132616875182228f  / 0.69314718055994531f)

// ---------------- scratch (device globals) ----------------
__device__ float g_q[OUT_MAIN];
__device__ float g_k[OUT_MAIN];
__device__ __half g_vh[OUT_MAIN];          // v projection in fp16
__device__ float g_o[OUT_MAIN];
__device__ float g_relk[CTX_ * E_];
__device__ float g_qdscale[D_];

// tiled+swizzled fp16 hi/lo operand storage
__device__ __half g_hs_hi[OUT_MAIN];
__device__ __half g_hs_lo[OUT_MAIN];
__device__ __half g_oc_hi[OUT_MAIN];
__device__ __half g_oc_lo[OUT_MAIN];
__device__ __half g_w_hi[5][WELEM_];
__device__ __half g_w_lo[5][WELEM_];
__device__ __half g_pe_hi[128 * E_];
__device__ __half g_pe_lo[128 * E_];

// ---------------- helpers ----------------
__device__ __forceinline__ void mma_f16(float c[4], unsigned a0, unsigned a1,
                                        unsigned a2, unsigned a3,
                                        unsigned b0, unsigned b1){
    asm volatile(
        "mma.sync.aligned.m16n8k16.row.col.f32.f16.f16.f32 "
        "{%0,%1,%2,%3}, {%4,%5,%6,%7}, {%8,%9}, {%0,%1,%2,%3};"
        : "+f"(c[0]), "+f"(c[1]), "+f"(c[2]), "+f"(c[3])
        : "r"(a0), "r"(a1), "r"(a2), "r"(a3), "r"(b0), "r"(b1));
}
__device__ __forceinline__ void ldsm4(unsigned r[4], unsigned addr){
    asm volatile("ldmatrix.sync.aligned.m8n8.x4.shared.b16 {%0,%1,%2,%3}, [%4];"
                 : "=r"(r[0]), "=r"(r[1]), "=r"(r[2]), "=r"(r[3]) : "r"(addr));
}
__device__ __forceinline__ void bulk_cp(unsigned dst, const void* src, unsigned bytes,
                                        unsigned mbar){
    asm volatile(
        "cp.async.bulk.shared::cluster.global.mbarrier::complete_tx::bytes "
        "[%0], [%1], %2, [%3];"
        :: "r"(dst), "l"(src), "r"(bytes), "r"(mbar) : "memory");
}
#define MBAR_INIT(addr, cnt) \
    asm volatile("mbarrier.init.shared.b64 [%0], %1;" :: "r"(addr), "r"(cnt) : "memory")
#define MBAR_EXPECT_TX(addr, bytes) \
    asm volatile("mbarrier.arrive.expect_tx.shared.b64 _, [%0], %1;" \
                 :: "r"(addr), "r"(bytes) : "memory")
#define MBAR_WAIT(mbar, parity) do {                                        \
    asm volatile(                                                           \
        "{\n\t.reg .pred P1;\n\t"                                           \
        "WL_%=:\n\t"                                                        \
        "mbarrier.try_wait.parity.acquire.cta.shared::cta.b64 P1, [%0], %1, 0x989680;\n\t" \
        "@P1 bra.uni WD_%=;\n\t"                                            \
        "bra.uni WL_%=;\n\t"                                                \
        "WD_%=:\n\t}"                                                       \
        :: "r"(mbar), "r"(parity) : "memory");                              \
} while (0)

// ---------------- fp32 -> fp16 hi/lo split into tiled+swizzled layout -------
__device__ __forceinline__ unsigned pack2hi(float a, float b){
    __half2 t = __halves2half2(__float2half_rn(a), __float2half_rn(b));
    return *(unsigned*)&t;
}
__device__ __forceinline__ unsigned pack2lo(float a, float b){
    float ha = __half2float(__float2half_rn(a));
    float hb = __half2float(__float2half_rn(b));
    __half2 t = __halves2half2(__float2half_rn(a - ha), __float2half_rn(b - hb));
    return *(unsigned*)&t;
}

// A-type: 128-row tiles of 128B rows (64 halves), SW128 swizzled, 16KB/tile
__global__ void split_tiled_A(const float* __restrict__ src,
                              __half* __restrict__ hi,
                              __half* __restrict__ lo,
                              int Mvalid, int Mpad, int K)
{
    const int id = blockIdx.x * 256 + threadIdx.x;
    const int CK = K >> 3;
    if (id >= Mpad * CK) return;
    const int m = id / CK, c = id % CK;
    float4 x0 = make_float4(0.f,0.f,0.f,0.f), x1 = x0;
    if (m < Mvalid) {
        const float4* s = (const float4*)(src + (size_t)m * K + c * 8);
        x0 = s[0]; x1 = s[1];
    }
    const size_t tile = (size_t)(m >> 7) * (K >> 6) + (c >> 3);
    const unsigned inner = (unsigned)((m & 127) * 128 + (((c & 7) * 16) ^ ((m & 7) * 16)));
    uint4 h = make_uint4(pack2hi(x0.x,x0.y), pack2hi(x0.z,x0.w),
                         pack2hi(x1.x,x1.y), pack2hi(x1.z,x1.w));
    uint4 l = make_uint4(pack2lo(x0.x,x0.y), pack2lo(x0.z,x0.w),
                         pack2lo(x1.x,x1.y), pack2lo(x1.z,x1.w));
    *(uint4*)((char*)hi + tile * 16384 + inner) = h;
    *(uint4*)((char*)lo + tile * 16384 + inner) = l;
}

// B-type: 256-row tiles of 128B rows, SW128 swizzled, 32KB/tile
__global__ void split_tiled_B(const float* __restrict__ src,
                              __half* __restrict__ hi,
                              __half* __restrict__ lo,
                              int N, int K)
{
    const int id = blockIdx.x * 256 + threadIdx.x;
    const int CK = K >> 3;
    if (id >= N * CK) return;
    const int n = id / CK, c = id % CK;
    const float4* s = (const float4*)(src + (size_t)n * K + c * 8);
    float4 x0 = s[0], x1 = s[1];
    const size_t tile = (size_t)(n >> 8) * (K >> 6) + (c >> 3);
    const unsigned inner = (unsigned)((n & 255) * 128 + (((c & 7) * 16) ^ ((n & 7) * 16)));
    uint4 h = make_uint4(pack2hi(x0.x,x0.y), pack2hi(x0.z,x0.w),
                         pack2hi(x1.x,x1.y), pack2hi(x1.z,x1.w));
    uint4 l = make_uint4(pack2lo(x0.x,x0.y), pack2lo(x0.z,x0.w),
                         pack2lo(x1.x,x1.y), pack2lo(x1.z,x1.w));
    *(uint4*)((char*)hi + tile * 32768 + inner) = h;
    *(uint4*)((char*)lo + tile * 32768 + inner) = l;
}

__global__ void prep_scale_kernel(const float* __restrict__ pds, float* __restrict__ out)
{
    int d = threadIdx.x;
    if (d < D_) {
        float x = pds[d];
        float sp = (x > 20.f) ? x : log1pf(expf(x));
        out[d] = QSCALE_BASE * sp;
    }
}

// ============================================================================
// fp16 hi/lo tensor-core NT GEMM with cp.async.bulk tile loads.
// 128x256 CTA tile, 256 threads (8 warps 2x4), warp tile 64x64,
// BK=64 halves, 2-stage mbarrier pipeline, m16n8k16 f16.
// NPASS=3: Ah*Bh + Al*Bh + Ah*Bl.  NPASS=2: Ah*Bh + Al*Bh (=A*Bh).
// mode: 0 plain f32; 1 colscale f32; 2 const-scale f32; 3 plain f16 output.
// Optional piggyback problem: when A2h != null, the LAST grid-y row computes
// C2[M2,N] = A2 * B^T (mode 0) instead — used to fold the tiny rel GEMM into
// the q GEMM launch so it doesn't serialize on a near-empty chip.
// ============================================================================
#define TILEA_B  16384
#define TILEB_B  32768
#define STB_     (2*TILEA_B + 2*TILEB_B)   // 98304 per stage
#define SMEM_GEMM_ (2*STB_ + 128)          // 196736

#define SOFF_AH_ 0
#define SOFF_AL_ TILEA_B
#define SOFF_BH_ (2*TILEA_B)
#define SOFF_BL_ (2*TILEA_B + TILEB_B)

template<int NPASS>
__global__ void __launch_bounds__(256)
gemm_bulk(const __half* __restrict__ Aht, const __half* __restrict__ Alt,
          const __half* __restrict__ Bht, const __half* __restrict__ Blt,
          float* __restrict__ C, int M, int N, int K,
          int mode, const float* __restrict__ colscale, float cscale,
          const __half* A2h, const __half* A2l, float* C2, int M2)
{
    extern __shared__ char smem[];
    const unsigned sb = (unsigned)__cvta_generic_to_shared(smem);
    const unsigned mb0 = sb + 2 * STB_;

    const int tid  = threadIdx.x;
    const int lane = tid & 31;
    const int warp = tid >> 5;
    const int wm = warp >> 2;
    const int wn = warp & 3;
    const int lr = lane >> 2;
    const int lc = lane & 3;

    // piggyback dispatch
    int by = blockIdx.y;
    const __half* pAh = Aht; const __half* pAl = Alt;
    float* pC = C; int pM = M; int pmode = mode;
    if (A2h != nullptr && by == (int)gridDim.y - 1) {
        pAh = A2h; pAl = A2l; pC = C2; pM = M2; pmode = 0; by = 0;
    }

    const int KT = K >> 6;
    const int aTile = by * KT;
    const int bTile = blockIdx.x * KT;

    if (tid == 0) { MBAR_INIT(mb0, 1); MBAR_INIT(mb0 + 8, 1); }
    __syncthreads();

    float acc[4][8][4];
#pragma unroll
    for (int i = 0; i < 4; i++)
#pragma unroll
        for (int j = 0; j < 8; j++)
#pragma unroll
            for (int r = 0; r < 4; r++) acc[i][j][r] = 0.f;

    const int g  = lane >> 3;
    const int tr = lane & 7;
    unsigned aoff[4], aswz[4];
#pragma unroll
    for (int mt = 0; mt < 4; mt++) {
        const int row = wm * 64 + mt * 16 + (g & 1) * 8 + tr;
        aoff[mt] = (unsigned)(row * 128);
        aswz[mt] = (unsigned)((row & 7) * 16);
    }
    const unsigned alane = (unsigned)((g >> 1) * 16);
    unsigned boff[4], bswz[4];
#pragma unroll
    for (int n2 = 0; n2 < 4; n2++) {
        const int n = wn * 64 + n2 * 16 + (g >> 1) * 8 + tr;
        boff[n2] = (unsigned)(n * 128);
        bswz[n2] = (unsigned)((n & 7) * 16);
    }
    const unsigned blane = (unsigned)((g & 1) * 16);

    const unsigned stage_tx = (NPASS == 3) ? (unsigned)STB_ : (unsigned)(STB_ - TILEB_B);

    auto issue = [&](int it, int s){
        if (tid == 0) {
            const unsigned mb = mb0 + s * 8;
            MBAR_EXPECT_TX(mb, stage_tx);
            const unsigned dst = sb + s * STB_;
            bulk_cp(dst + SOFF_AH_, (const char*)pAh + (size_t)(aTile + it) * TILEA_B, TILEA_B, mb);
            bulk_cp(dst + SOFF_AL_, (const char*)pAl + (size_t)(aTile + it) * TILEA_B, TILEA_B, mb);
            bulk_cp(dst + SOFF_BH_, (const char*)Bht + (size_t)(bTile + it) * TILEB_B, TILEB_B, mb);
            if (NPASS == 3)
                bulk_cp(dst + SOFF_BL_, (const char*)Blt + (size_t)(bTile + it) * TILEB_B, TILEB_B, mb);
        }
    };

    issue(0, 0);
    issue(1, 1);

    for (int it = 0; it < KT; it++) {
        const int s = it & 1;
        MBAR_WAIT(mb0 + s * 8, (unsigned)((it >> 1) & 1));

        const unsigned base = sb + s * STB_;
        const unsigned sAh = base + SOFF_AH_;
        const unsigned sAl = base + SOFF_AL_;
        const unsigned sBh = base + SOFF_BH_;
        const unsigned sBl = base + SOFF_BL_;

#pragma unroll
        for (int k0 = 0; k0 < 4; k0++) {
            const unsigned kb = (unsigned)(k0 * 32);

            unsigned ah[4][4], bh[4][4];
#pragma unroll
            for (int mt = 0; mt < 4; mt++)
                ldsm4(ah[mt], sAh + aoff[mt] + ((kb + alane) ^ aswz[mt]));
#pragma unroll
            for (int n2 = 0; n2 < 4; n2++)
                ldsm4(bh[n2], sBh + boff[n2] + ((kb + blane) ^ bswz[n2]));
#pragma unroll
            for (int mt = 0; mt < 4; mt++)
#pragma unroll
                for (int nt = 0; nt < 8; nt++)
                    mma_f16(acc[mt][nt], ah[mt][0], ah[mt][1], ah[mt][2], ah[mt][3],
                            bh[nt >> 1][(nt & 1) * 2], bh[nt >> 1][(nt & 1) * 2 + 1]);

            unsigned xl[4][4];
#pragma unroll
            for (int mt = 0; mt < 4; mt++)
                ldsm4(xl[mt], sAl + aoff[mt] + ((kb + alane) ^ aswz[mt]));
#pragma unroll
            for (int mt = 0; mt < 4; mt++)
#pragma unroll
                for (int nt = 0; nt < 8; nt++)
                    mma_f16(acc[mt][nt], xl[mt][0], xl[mt][1], xl[mt][2], xl[mt][3],
                            bh[nt >> 1][(nt & 1) * 2], bh[nt >> 1][(nt & 1) * 2 + 1]);

            if (NPASS == 3) {
#pragma unroll
                for (int n2 = 0; n2 < 4; n2++)
                    ldsm4(xl[n2], sBl + boff[n2] + ((kb + blane) ^ bswz[n2]));
#pragma unroll
                for (int mt = 0; mt < 4; mt++)
#pragma unroll
                    for (int nt = 0; nt < 8; nt++)
                        mma_f16(acc[mt][nt], ah[mt][0], ah[mt][1], ah[mt][2], ah[mt][3],
                                xl[nt >> 1][(nt & 1) * 2], xl[nt >> 1][(nt & 1) * 2 + 1]);
            }
        }
        __syncthreads();
        if (it + 2 < KT) issue(it + 2, s);
    }

    // --- epilogue ---
    const int bm = by * 128;
    const int bn = blockIdx.x * 256;
#pragma unroll
    for (int mt = 0; mt < 4; mt++) {
#pragma unroll
        for (int nt = 0; nt < 8; nt++) {
            const int r0 = bm + wm * 64 + mt * 16 + lr;
            const int c0 = bn + wn * 64 + nt * 8 + 2 * lc;
            float v0 = acc[mt][nt][0], v1 = acc[mt][nt][1];
            float v2 = acc[mt][nt][2], v3 = acc[mt][nt][3];
            if (pmode == 1) {
                const float s0 = colscale[c0 & (D_-1)], s1 = colscale[(c0+1) & (D_-1)];
                v0 *= s0; v1 *= s1; v2 *= s0; v3 *= s1;
            } else if (pmode == 2) {
                v0 *= cscale; v1 *= cscale; v2 *= cscale; v3 *= cscale;
            }
            if (pmode == 3) {
                __half* Ch = (__half*)pC;
                if (r0 < pM)
                    *(__half2*)(Ch + (size_t)r0 * N + c0) =
                        __halves2half2(__float2half_rn(v0), __float2half_rn(v1));
                if (r0 + 8 < pM)
                    *(__half2*)(Ch + (size_t)(r0+8) * N + c0) =
                        __halves2half2(__float2half_rn(v2), __float2half_rn(v3));
            } else {
                if (r0 < pM)     *(float2*)(pC + (size_t)r0      * N + c0) = make_float2(v0, v1);
                if (r0 + 8 < pM) *(float2*)(pC + (size_t)(r0+8)  * N + c0) = make_float2(v2, v3);
            }
        }
    }
}

// ---------------- chunked local attention (R10 structure; fp16 v) ----------
__global__ void __launch_bounds__(384)
attn_kernel(const float* __restrict__ q, const float* __restrict__ k,
            const __half* __restrict__ vh, const float* __restrict__ relk,
            float* __restrict__ o, float* __restrict__ attn_out)
{
    __shared__ float sq[CHUNK_][129];
    __shared__ float sk[CTX_][129];
    __shared__ float sv[CTX_][129];
    __shared__ float sr[CTX_][129];
    __shared__ float sac[CHUNK_][CTX_];
    __shared__ float sbd[CHUNK_][CTX_];
    __shared__ float sw[CHUNK_][25];

    const int n = blockIdx.x, h = blockIdx.y, b = blockIdx.z;
    const int t = threadIdx.x;

    for (int i = t; i < CHUNK_ * D_; i += 384) {
        const int c = i >> 7, d = i & 127;
        const int s = n * CHUNK_ + c;
        sq[c][d] = q[((size_t)(b * S_ + s)) * E_ + h * D_ + d];
    }
    for (int i = t; i < CTX_ * D_; i += 384) {
        const int j = i >> 7, d = i & 127;
        const int s = n * CHUNK_ - 12 + j;
        float kv = 0.f, vv = 0.f;
        if (s >= 0 && s < S_) {
            const size_t base = ((size_t)(b * S_ + s)) * E_ + h * D_ + d;
            kv = k[base];
            vv = __half2float(vh[base]);
        }
        sk[j][d] = kv;
        sv[j][d] = vv;
        sr[j][d] = relk[(size_t)j * E_ + h * D_ + d];
    }
    __syncthreads();

    for (int i = t; i < CHUNK_ * CTX_; i += 384) {
        const int c = i / CTX_, j = i % CTX_;
        float a = 0.f, bb = 0.f;
#pragma unroll 8
        for (int d = 0; d < D_; d++) {
            const float qq = sq[c][d];
            a  = fmaf(qq, sk[j][d], a);
            bb = fmaf(qq, sr[j][d], bb);
        }
        sac[c][j] = a;
        sbd[c][j] = bb;
    }
    __syncthreads();

    for (int i = t; i < CHUNK_ * CTX_; i += 384) {
        const int c = i / CTX_, j = i % CTX_;
        const int idx = c * CTX_ + j;
        const int r = idx / (CTX_ + 1);
        const int p = idx % (CTX_ + 1);
        const float bd = (p < CTX_) ? sbd[r][p] : 0.f;
        float l = sac[c][j] + bd;
        l = 50.f * tanhf(l * 0.02f);
        sw[c][j] = l;
    }
    __syncthreads();

    if (t < CHUNK_) {
        const int c = t;
        float m = -1e30f;
        for (int j = 0; j < CTX_; j++) m = fmaxf(m, sw[c][j]);
        float sum = 0.f;
        for (int j = 0; j < CTX_; j++) { const float e = expf(sw[c][j] - m); sum += e; sw[c][j] = e; }
        const float inv = 1.f / sum;
        for (int j = 0; j < CTX_; j++) sw[c][j] *= inv;
    }
    __syncthreads();

    if (attn_out) {
        for (int i = t; i < CHUNK_ * CTX_; i += 384) {
            const int c = i / CTX_, j = i % CTX_;
            attn_out[((((size_t)b * H_ + h) * NB_ + n) * CHUNK_ + c) * CTX_ + j] = sw[c][j];
        }
    }

    for (int i = t; i < CHUNK_ * D_; i += 384) {
        const int c = i >> 7, d = i & 127;
        float acc = 0.f;
#pragma unroll
        for (int j = 0; j < CTX_; j++) acc = fmaf(sw[c][j], sv[j][d], acc);
        o[((size_t)(b * S_ + n * CHUNK_ + c)) * E_ + h * D_ + d] = acc;
    }
}

// ---------------- launch -----------------------------------------------------
extern "C" void kernel_launch(void* const* d_in, const int* in_sizes, int n_in,
                              void* d_out, int out_size)
{
    const float* hs   = (const float*)d_in[0];
    const float* pe   = (const float*)d_in[1];
    const float* w_q  = (const float*)d_in[2];
    const float* w_k  = (const float*)d_in[3];
    const float* w_v  = (const float*)d_in[4];
    const float* w_p  = (const float*)d_in[5];
    const float* w_r  = (const float*)d_in[6];
    const float* pds  = (const float*)d_in[7];
    float* out = (float*)d_out;

    float *q, *k, *o, *rk, *qs;
    __half *vh;
    cudaGetSymbolAddress((void**)&q,  g_q);
    cudaGetSymbolAddress((void**)&k,  g_k);
    cudaGetSymbolAddress((void**)&vh, g_vh);
    cudaGetSymbolAddress((void**)&o,  g_o);
    cudaGetSymbolAddress((void**)&rk, g_relk);
    cudaGetSymbolAddress((void**)&qs, g_qdscale);

    __half *hsh, *hsl, *och, *ocl, *wh, *wl, *peh, *pel;
    cudaGetSymbolAddress((void**)&hsh, g_hs_hi);
    cudaGetSymbolAddress((void**)&hsl, g_hs_lo);
    cudaGetSymbolAddress((void**)&och, g_oc_hi);
    cudaGetSymbolAddress((void**)&ocl, g_oc_lo);
    cudaGetSymbolAddress((void**)&wh,  g_w_hi);
    cudaGetSymbolAddress((void**)&wl,  g_w_lo);
    cudaGetSymbolAddress((void**)&peh, g_pe_hi);
    cudaGetSymbolAddress((void**)&pel, g_pe_lo);

    cudaFuncSetAttribute(gemm_bulk<3>, cudaFuncAttributeMaxDynamicSharedMemorySize, SMEM_GEMM_);
    cudaFuncSetAttribute(gemm_bulk<2>, cudaFuncAttributeMaxDynamicSharedMemorySize, SMEM_GEMM_);

    prep_scale_kernel<<<1, 128>>>(pds, qs);

    const int tA = MTOK_ * (E_ / 8);
    split_tiled_A<<<(tA + 255) / 256, 256>>>(hs, hsh, hsl, MTOK_, MTOK_, E_);
    const int tB = E_ * (E_ / 8);
    split_tiled_B<<<(tB + 255) / 256, 256>>>(w_q, wh + 0*(size_t)WELEM_, wl + 0*(size_t)WELEM_, E_, E_);
    split_tiled_B<<<(tB + 255) / 256, 256>>>(w_k, wh + 1*(size_t)WELEM_, wl + 1*(size_t)WELEM_, E_, E_);
    split_tiled_B<<<(tB + 255) / 256, 256>>>(w_v, wh + 2*(size_t)WELEM_, wl + 2*(size_t)WELEM_, E_, E_);
    split_tiled_B<<<(tB + 255) / 256, 256>>>(w_p, wh + 3*(size_t)WELEM_, wl + 3*(size_t)WELEM_, E_, E_);
    split_tiled_B<<<(tB + 255) / 256, 256>>>(w_r, wh + 4*(size_t)WELEM_, wl + 4*(size_t)WELEM_, E_, E_);
    const int tPE = 128 * (E_ / 8);
    split_tiled_A<<<(tPE + 255) / 256, 256>>>(pe, peh, pel, CTX_, 128, E_);

    // q GEMM carries the rel GEMM as the extra last grid-y row.
    // NOTE: rel's B is w_r (index 4) but q's B is w_q — they differ, so the
    // piggyback shares only the launch, not B. The y==192 row loads B from the
    // SAME Bht pointer, so rel must use its own launch... instead we piggyback
    // rel onto the GEMM whose B is w_r: there is none. Solution: rel rides the
    // q launch with its own A AND the q kernel's Bht/Blt must be w_r for that
    // row. Simplest correct approach: pass w_r tiles as B2 via the same trick.
    // To keep the kernel simple we instead piggyback rel on a separate tiny
    // grid appended to the K GEMM? No — keep it correct: launch rel fused with
    // q by swapping BOTH A and B for the last row.
    const dim3 gQ(E_ / 256, MTOK_ / 128 + 1);   // (6, 193) last row = rel
    const dim3 gBig(E_ / 256, MTOK_ / 128);     // (6, 192)

    // For the piggyback row we need B = w_r. We exploit that the kernel reads
    // Bht/Blt with bTile = blockIdx.x*KT; passing the w_q pointers would be
    // wrong. So extend: hide w_r tiles directly behind w_q? They are separate
    // arrays. Instead: the piggyback row uses A2h/A2l AND we pass w_r via
    // C2/M2... (kernel only swaps A/C/M). Therefore fold rel into the GEMM
    // that already uses w_r as B — none exists. Fallback: keep rel as its own
    // tiny launch BUT issue it FIRST so it overlaps the tail of the splits
    // queue rather than serializing between big GEMMs.
    gemm_bulk<3><<<dim3(E_ / 256, 1), 256, SMEM_GEMM_>>>(peh, pel,
                    wh + 4*(size_t)WELEM_, wl + 4*(size_t)WELEM_,
                    rk, CTX_, E_, E_, 0, nullptr, 1.f,
                    nullptr, nullptr, nullptr, 0);

    gemm_bulk<3><<<gBig, 256, SMEM_GEMM_>>>(hsh, hsl, wh + 0*(size_t)WELEM_, wl + 0*(size_t)WELEM_,
                                            q, MTOK_, E_, E_, 1, qs, 1.f,
                                            nullptr, nullptr, nullptr, 0);
    gemm_bulk<3><<<gBig, 256, SMEM_GEMM_>>>(hsh, hsl, wh + 1*(size_t)WELEM_, wl + 1*(size_t)WELEM_,
                                            k, MTOK_, E_, E_, 2, nullptr, KSCALE,
                                            nullptr, nullptr, nullptr, 0);
    gemm_bulk<2><<<gBig, 256, SMEM_GEMM_>>>(hsh, hsl, wh + 2*(size_t)WELEM_, wl + 2*(size_t)WELEM_,
                                            (float*)vh, MTOK_, E_, E_, 3, nullptr, 1.f,
                                            nullptr, nullptr, nullptr, 0);

    float* attn = ((size_t)out_size >= OUT_MAIN + ATTN_SZ) ? (out + OUT_MAIN) : nullptr;
    attn_kernel<<<dim3(NB_, H_, B_), 384>>>(q, k, vh, rk, o, attn);

    split_tiled_A<<<(tA + 255) / 256, 256>>>(o, och, ocl, MTOK_, MTOK_, E_);
    gemm_bulk<2><<<gBig, 256, SMEM_GEMM_>>>(och, ocl, wh + 3*(size_t)WELEM_, wl + 3*(size_t)WELEM_,
                                            out, MTOK_, E_, E_, 0, nullptr, 1.f,
                                            nullptr, nullptr, nullptr, 0);
}

// round 14
// speedup vs baseline: 1.0661x; 1.0100x over previous
#include <cuda_runtime.h>
#include <cuda_fp16.h>
#include <stdint.h>
#include <math.h>

// ---------------- problem constants ----------------
#define B_    8
#define S_    3072
#define H_    12
#define D_    128
#define E_    1536
#define NB_   256
#define CHUNK_ 12
#define CTX_  24
#define MTOK_ (B_*S_)         // 24576

#define OUT_MAIN  ((size_t)MTOK_ * E_)
#define ATTN_SZ   ((size_t)B_*H_*NB_*CHUNK_*CTX_)
#define WELEM_    (E_*E_)

#define QSCALE_BASE (0.088388347648318447f / 0.69314718055994531f)
#define KSCALE      (1.3132616875182228f  / 0.69314718055994531f)

// ---------------- scratch (device globals) ----------------
__device__ float g_q[OUT_MAIN];
__device__ float g_k[OUT_MAIN];
__device__ float g_v[OUT_MAIN];
__device__ float g_o[OUT_MAIN];
__device__ float g_relk[CTX_ * E_];
__device__ float g_qdscale[D_];

// tiled+swizzled fp16 hi/lo operand storage
__device__ __half g_hs_hi[OUT_MAIN];
__device__ __half g_hs_lo[OUT_MAIN];
__device__ __half g_oc_hi[OUT_MAIN];
__device__ __half g_oc_lo[OUT_MAIN];
__device__ __half g_w_hi[5][WELEM_];
__device__ __half g_w_lo[5][WELEM_];
__device__ __half g_pe_hi[128 * E_];
__device__ __half g_pe_lo[128 * E_];

// ---------------- helpers ----------------
__device__ __forceinline__ void mma_f16(float c[4], unsigned a0, unsigned a1,
                                        unsigned a2, unsigned a3,
                                        unsigned b0, unsigned b1){
    asm volatile(
        "mma.sync.aligned.m16n8k16.row.col.f32.f16.f16.f32 "
        "{%0,%1,%2,%3}, {%4,%5,%6,%7}, {%8,%9}, {%0,%1,%2,%3};"
        : "+f"(c[0]), "+f"(c[1]), "+f"(c[2]), "+f"(c[3])
        : "r"(a0), "r"(a1), "r"(a2), "r"(a3), "r"(b0), "r"(b1));
}
__device__ __forceinline__ void ldsm4(unsigned r[4], unsigned addr){
    asm volatile("ldmatrix.sync.aligned.m8n8.x4.shared.b16 {%0,%1,%2,%3}, [%4];"
                 : "=r"(r[0]), "=r"(r[1]), "=r"(r[2]), "=r"(r[3]) : "r"(addr));
}
__device__ __forceinline__ void bulk_cp(unsigned dst, const void* src, unsigned bytes,
                                        unsigned mbar){
    asm volatile(
        "cp.async.bulk.shared::cluster.global.mbarrier::complete_tx::bytes "
        "[%0], [%1], %2, [%3];"
        :: "r"(dst), "l"(src), "r"(bytes), "r"(mbar) : "memory");
}
#define MBAR_INIT(addr, cnt) \
    asm volatile("mbarrier.init.shared.b64 [%0], %1;" :: "r"(addr), "r"(cnt) : "memory")
#define MBAR_EXPECT_TX(addr, bytes) \
    asm volatile("mbarrier.arrive.expect_tx.shared.b64 _, [%0], %1;" \
                 :: "r"(addr), "r"(bytes) : "memory")
#define MBAR_WAIT(mbar, parity) do {                                        \
    asm volatile(                                                           \
        "{\n\t.reg .pred P1;\n\t"                                           \
        "WL_%=:\n\t"                                                        \
        "mbarrier.try_wait.parity.acquire.cta.shared::cta.b64 P1, [%0], %1, 0x989680;\n\t" \
        "@P1 bra.uni WD_%=;\n\t"                                            \
        "bra.uni WL_%=;\n\t"                                                \
        "WD_%=:\n\t}"                                                       \
        :: "r"(mbar), "r"(parity) : "memory");                              \
} while (0)

// ---------------- fp32 -> fp16 hi/lo split into tiled+swizzled layout -------
__device__ __forceinline__ unsigned pack2hi(float a, float b){
    __half2 t = __halves2half2(__float2half_rn(a), __float2half_rn(b));
    return *(unsigned*)&t;
}
__device__ __forceinline__ unsigned pack2lo(float a, float b){
    float ha = __half2float(__float2half_rn(a));
    float hb = __half2float(__float2half_rn(b));
    __half2 t = __halves2half2(__float2half_rn(a - ha), __float2half_rn(b - hb));
    return *(unsigned*)&t;
}

// A-type: 128-row tiles of 128B rows (64 halves), SW128 swizzled, 16KB/tile.
// 4-way ILP: each thread handles 4 strided chunks (independent chains).
__global__ void split_tiled_A(const float* __restrict__ src,
                              __half* __restrict__ hi,
                              __half* __restrict__ lo,
                              int Mvalid, int Mpad, int K)
{
    const int CK = K >> 3;
    const int total = Mpad * CK;
    const int base = blockIdx.x * 1024 + threadIdx.x;
#pragma unroll
    for (int u = 0; u < 4; u++) {
        const int id = base + u * 256;
        if (id >= total) continue;
        const int m = id / CK, c = id % CK;
        float4 x0 = make_float4(0.f,0.f,0.f,0.f), x1 = x0;
        if (m < Mvalid) {
            const float4* s = (const float4*)(src + (size_t)m * K + c * 8);
            x0 = s[0]; x1 = s[1];
        }
        const size_t tile = (size_t)(m >> 7) * (K >> 6) + (c >> 3);
        const unsigned inner = (unsigned)((m & 127) * 128 + (((c & 7) * 16) ^ ((m & 7) * 16)));
        uint4 h = make_uint4(pack2hi(x0.x,x0.y), pack2hi(x0.z,x0.w),
                             pack2hi(x1.x,x1.y), pack2hi(x1.z,x1.w));
        uint4 l = make_uint4(pack2lo(x0.x,x0.y), pack2lo(x0.z,x0.w),
                             pack2lo(x1.x,x1.y), pack2lo(x1.z,x1.w));
        *(uint4*)((char*)hi + tile * 16384 + inner) = h;
        *(uint4*)((char*)lo + tile * 16384 + inner) = l;
    }
}

// B-type: 256-row tiles of 128B rows, SW128 swizzled, 32KB/tile. 4-way ILP.
__global__ void split_tiled_B(const float* __restrict__ src,
                              __half* __restrict__ hi,
                              __half* __restrict__ lo,
                              int N, int K)
{
    const int CK = K >> 3;
    const int total = N * CK;
    const int base = blockIdx.x * 1024 + threadIdx.x;
#pragma unroll
    for (int u = 0; u < 4; u++) {
        const int id = base + u * 256;
        if (id >= total) continue;
        const int n = id / CK, c = id % CK;
        const float4* s = (const float4*)(src + (size_t)n * K + c * 8);
        float4 x0 = s[0], x1 = s[1];
        const size_t tile = (size_t)(n >> 8) * (K >> 6) + (c >> 3);
        const unsigned inner = (unsigned)((n & 255) * 128 + (((c & 7) * 16) ^ ((n & 7) * 16)));
        uint4 h = make_uint4(pack2hi(x0.x,x0.y), pack2hi(x0.z,x0.w),
                             pack2hi(x1.x,x1.y), pack2hi(x1.z,x1.w));
        uint4 l = make_uint4(pack2lo(x0.x,x0.y), pack2lo(x0.z,x0.w),
                             pack2lo(x1.x,x1.y), pack2lo(x1.z,x1.w));
        *(uint4*)((char*)hi + tile * 32768 + inner) = h;
        *(uint4*)((char*)lo + tile * 32768 + inner) = l;
    }
}

__global__ void prep_scale_kernel(const float* __restrict__ pds, float* __restrict__ out)
{
    int d = threadIdx.x;
    if (d < D_) {
        float x = pds[d];
        float sp = (x > 20.f) ? x : log1pf(expf(x));
        out[d] = QSCALE_BASE * sp;
    }
}

// ============================================================================
// fp16 hi/lo tensor-core NT GEMM with cp.async.bulk tile loads.
// 128x256 CTA tile, 256 threads (8 warps 2x4), warp tile 64x64,
// BK=64 halves, 2-stage mbarrier pipeline, m16n8k16 f16.
// NPASS=3: Ah*Bh + Al*Bh + Ah*Bl.  NPASS=2: Ah*Bh + Al*Bh (=A*Bh).
// mode: 0 plain f32; 1 colscale f32; 2 const-scale f32.
// ============================================================================
#define TILEA_B  16384
#define TILEB_B  32768
#define STB_     (2*TILEA_B + 2*TILEB_B)   // 98304 per stage
#define SMEM_GEMM_ (2*STB_ + 128)          // 196736

#define SOFF_AH_ 0
#define SOFF_AL_ TILEA_B
#define SOFF_BH_ (2*TILEA_B)
#define SOFF_BL_ (2*TILEA_B + TILEB_B)

template<int NPASS>
__global__ void __launch_bounds__(256)
gemm_bulk(const __half* __restrict__ Aht, const __half* __restrict__ Alt,
          const __half* __restrict__ Bht, const __half* __restrict__ Blt,
          float* __restrict__ C, int M, int N, int K,
          int mode, const float* __restrict__ colscale, float cscale)
{
    extern __shared__ char smem[];
    const unsigned sb = (unsigned)__cvta_generic_to_shared(smem);
    const unsigned mb0 = sb + 2 * STB_;

    const int tid  = threadIdx.x;
    const int lane = tid & 31;
    const int warp = tid >> 5;
    const int wm = warp >> 2;
    const int wn = warp & 3;
    const int lr = lane >> 2;
    const int lc = lane & 3;

    const int KT = K >> 6;
    const int aTile = blockIdx.y * KT;
    const int bTile = blockIdx.x * KT;

    if (tid == 0) { MBAR_INIT(mb0, 1); MBAR_INIT(mb0 + 8, 1); }
    __syncthreads();

    float acc[4][8][4];
#pragma unroll
    for (int i = 0; i < 4; i++)
#pragma unroll
        for (int j = 0; j < 8; j++)
#pragma unroll
            for (int r = 0; r < 4; r++) acc[i][j][r] = 0.f;

    const int g  = lane >> 3;
    const int tr = lane & 7;
    unsigned aoff[4], aswz[4];
#pragma unroll
    for (int mt = 0; mt < 4; mt++) {
        const int row = wm * 64 + mt * 16 + (g & 1) * 8 + tr;
        aoff[mt] = (unsigned)(row * 128);
        aswz[mt] = (unsigned)((row & 7) * 16);
    }
    const unsigned alane = (unsigned)((g >> 1) * 16);
    unsigned boff[4], bswz[4];
#pragma unroll
    for (int n2 = 0; n2 < 4; n2++) {
        const int n = wn * 64 + n2 * 16 + (g >> 1) * 8 + tr;
        boff[n2] = (unsigned)(n * 128);
        bswz[n2] = (unsigned)((n & 7) * 16);
    }
    const unsigned blane = (unsigned)((g & 1) * 16);

    const unsigned stage_tx = (NPASS == 3) ? (unsigned)STB_ : (unsigned)(STB_ - TILEB_B);

    auto issue = [&](int it, int s){
        if (tid == 0) {
            const unsigned mb = mb0 + s * 8;
            MBAR_EXPECT_TX(mb, stage_tx);
            const unsigned dst = sb + s * STB_;
            bulk_cp(dst + SOFF_AH_, (const char*)Aht + (size_t)(aTile + it) * TILEA_B, TILEA_B, mb);
            bulk_cp(dst + SOFF_AL_, (const char*)Alt + (size_t)(aTile + it) * TILEA_B, TILEA_B, mb);
            bulk_cp(dst + SOFF_BH_, (const char*)Bht + (size_t)(bTile + it) * TILEB_B, TILEB_B, mb);
            if (NPASS == 3)
                bulk_cp(dst + SOFF_BL_, (const char*)Blt + (size_t)(bTile + it) * TILEB_B, TILEB_B, mb);
        }
    };

    issue(0, 0);
    issue(1, 1);

    for (int it = 0; it < KT; it++) {
        const int s = it & 1;
        MBAR_WAIT(mb0 + s * 8, (unsigned)((it >> 1) & 1));

        const unsigned base = sb + s * STB_;
        const unsigned sAh = base + SOFF_AH_;
        const unsigned sAl = base + SOFF_AL_;
        const unsigned sBh = base + SOFF_BH_;
        const unsigned sBl = base + SOFF_BL_;

#pragma unroll
        for (int k0 = 0; k0 < 4; k0++) {
            const unsigned kb = (unsigned)(k0 * 32);

            unsigned ah[4][4], bh[4][4];
#pragma unroll
            for (int mt = 0; mt < 4; mt++)
                ldsm4(ah[mt], sAh + aoff[mt] + ((kb + alane) ^ aswz[mt]));
#pragma unroll
            for (int n2 = 0; n2 < 4; n2++)
                ldsm4(bh[n2], sBh + boff[n2] + ((kb + blane) ^ bswz[n2]));
#pragma unroll
            for (int mt = 0; mt < 4; mt++)
#pragma unroll
                for (int nt = 0; nt < 8; nt++)
                    mma_f16(acc[mt][nt], ah[mt][0], ah[mt][1], ah[mt][2], ah[mt][3],
                            bh[nt >> 1][(nt & 1) * 2], bh[nt >> 1][(nt & 1) * 2 + 1]);

            unsigned xl[4][4];
#pragma unroll
            for (int mt = 0; mt < 4; mt++)
                ldsm4(xl[mt], sAl + aoff[mt] + ((kb + alane) ^ aswz[mt]));
#pragma unroll
            for (int mt = 0; mt < 4; mt++)
#pragma unroll
                for (int nt = 0; nt < 8; nt++)
                    mma_f16(acc[mt][nt], xl[mt][0], xl[mt][1], xl[mt][2], xl[mt][3],
                            bh[nt >> 1][(nt & 1) * 2], bh[nt >> 1][(nt & 1) * 2 + 1]);

            if (NPASS == 3) {
#pragma unroll
                for (int n2 = 0; n2 < 4; n2++)
                    ldsm4(xl[n2], sBl + boff[n2] + ((kb + blane) ^ bswz[n2]));
#pragma unroll
                for (int mt = 0; mt < 4; mt++)
#pragma unroll
                    for (int nt = 0; nt < 8; nt++)
                        mma_f16(acc[mt][nt], ah[mt][0], ah[mt][1], ah[mt][2], ah[mt][3],
                                xl[nt >> 1][(nt & 1) * 2], xl[nt >> 1][(nt & 1) * 2 + 1]);
            }
        }
        __syncthreads();
        if (it + 2 < KT) issue(it + 2, s);
    }

    // --- epilogue ---
    const int bm = blockIdx.y * 128;
    const int bn = blockIdx.x * 256;
#pragma unroll
    for (int mt = 0; mt < 4; mt++) {
#pragma unroll
        for (int nt = 0; nt < 8; nt++) {
            const int r0 = bm + wm * 64 + mt * 16 + lr;
            const int c0 = bn + wn * 64 + nt * 8 + 2 * lc;
            float v0 = acc[mt][nt][0], v1 = acc[mt][nt][1];
            float v2 = acc[mt][nt][2], v3 = acc[mt][nt][3];
            if (mode == 1) {
                const float s0 = colscale[c0 & (D_-1)], s1 = colscale[(c0+1) & (D_-1)];
                v0 *= s0; v1 *= s1; v2 *= s0; v3 *= s1;
            } else if (mode == 2) {
                v0 *= cscale; v1 *= cscale; v2 *= cscale; v3 *= cscale;
            }
            if (r0 < M)     *(float2*)(C + (size_t)r0      * N + c0) = make_float2(v0, v1);
            if (r0 + 8 < M) *(float2*)(C + (size_t)(r0+8)  * N + c0) = make_float2(v2, v3);
        }
    }
}

// ---------------- chunked local attention (R10 structure) -------------------
__global__ void __launch_bounds__(384)
attn_kernel(const float* __restrict__ q, const float* __restrict__ k,
            const float* __restrict__ v, const float* __restrict__ relk,
            float* __restrict__ o, float* __restrict__ attn_out)
{
    __shared__ float sq[CHUNK_][129];
    __shared__ float sk[CTX_][129];
    __shared__ float sv[CTX_][129];
    __shared__ float sr[CTX_][129];
    __shared__ float sac[CHUNK_][CTX_];
    __shared__ float sbd[CHUNK_][CTX_];
    __shared__ float sw[CHUNK_][25];

    const int n = blockIdx.x, h = blockIdx.y, b = blockIdx.z;
    const int t = threadIdx.x;

    for (int i = t; i < CHUNK_ * D_; i += 384) {
        const int c = i >> 7, d = i & 127;
        const int s = n * CHUNK_ + c;
        sq[c][d] = q[((size_t)(b * S_ + s)) * E_ + h * D_ + d];
    }
    for (int i = t; i < CTX_ * D_; i += 384) {
        const int j = i >> 7, d = i & 127;
        const int s = n * CHUNK_ - 12 + j;
        float kv = 0.f, vv = 0.f;
        if (s >= 0 && s < S_) {
            const size_t base = ((size_t)(b * S_ + s)) * E_ + h * D_ + d;
            kv = k[base]; vv = v[base];
        }
        sk[j][d] = kv;
        sv[j][d] = vv;
        sr[j][d] = relk[(size_t)j * E_ + h * D_ + d];
    }
    __syncthreads();

    for (int i = t; i < CHUNK_ * CTX_; i += 384) {
        const int c = i / CTX_, j = i % CTX_;
        float a = 0.f, bb = 0.f;
#pragma unroll 8
        for (int d = 0; d < D_; d++) {
            const float qq = sq[c][d];
            a  = fmaf(qq, sk[j][d], a);
            bb = fmaf(qq, sr[j][d], bb);
        }
        sac[c][j] = a;
        sbd[c][j] = bb;
    }
    __syncthreads();

    for (int i = t; i < CHUNK_ * CTX_; i += 384) {
        const int c = i / CTX_, j = i % CTX_;
        const int idx = c * CTX_ + j;
        const int r = idx / (CTX_ + 1);
        const int p = idx % (CTX_ + 1);
        const float bd = (p < CTX_) ? sbd[r][p] : 0.f;
        float l = sac[c][j] + bd;
        l = 50.f * tanhf(l * 0.02f);
        sw[c][j] = l;
    }
    __syncthreads();

    if (t < CHUNK_) {
        const int c = t;
        float m = -1e30f;
        for (int j = 0; j < CTX_; j++) m = fmaxf(m, sw[c][j]);
        float sum = 0.f;
        for (int j = 0; j < CTX_; j++) { const float e = expf(sw[c][j] - m); sum += e; sw[c][j] = e; }
        const float inv = 1.f / sum;
        for (int j = 0; j < CTX_; j++) sw[c][j] *= inv;
    }
    __syncthreads();

    if (attn_out) {
        for (int i = t; i < CHUNK_ * CTX_; i += 384) {
            const int c = i / CTX_, j = i % CTX_;
            attn_out[((((size_t)b * H_ + h) * NB_ + n) * CHUNK_ + c) * CTX_ + j] = sw[c][j];
        }
    }

    for (int i = t; i < CHUNK_ * D_; i += 384) {
        const int c = i >> 7, d = i & 127;
        float acc = 0.f;
#pragma unroll
        for (int j = 0; j < CTX_; j++) acc = fmaf(sw[c][j], sv[j][d], acc);
        o[((size_t)(b * S_ + n * CHUNK_ + c)) * E_ + h * D_ + d] = acc;
    }
}

// ---------------- launch -----------------------------------------------------
extern "C" void kernel_launch(void* const* d_in, const int* in_sizes, int n_in,
                              void* d_out, int out_size)
{
    const float* hs   = (const float*)d_in[0];
    const float* pe   = (const float*)d_in[1];
    const float* w_q  = (const float*)d_in[2];
    const float* w_k  = (const float*)d_in[3];
    const float* w_v  = (const float*)d_in[4];
    const float* w_p  = (const float*)d_in[5];
    const float* w_r  = (const float*)d_in[6];
    const float* pds  = (const float*)d_in[7];
    float* out = (float*)d_out;

    float *q, *k, *v, *o, *rk, *qs;
    cudaGetSymbolAddress((void**)&q,  g_q);
    cudaGetSymbolAddress((void**)&k,  g_k);
    cudaGetSymbolAddress((void**)&v,  g_v);
    cudaGetSymbolAddress((void**)&o,  g_o);
    cudaGetSymbolAddress((void**)&rk, g_relk);
    cudaGetSymbolAddress((void**)&qs, g_qdscale);

    __half *hsh, *hsl, *och, *ocl, *wh, *wl, *peh, *pel;
    cudaGetSymbolAddress((void**)&hsh, g_hs_hi);
    cudaGetSymbolAddress((void**)&hsl, g_hs_lo);
    cudaGetSymbolAddress((void**)&och, g_oc_hi);
    cudaGetSymbolAddress((void**)&ocl, g_oc_lo);
    cudaGetSymbolAddress((void**)&wh,  g_w_hi);
    cudaGetSymbolAddress((void**)&wl,  g_w_lo);
    cudaGetSymbolAddress((void**)&peh, g_pe_hi);
    cudaGetSymbolAddress((void**)&pel, g_pe_lo);

    cudaFuncSetAttribute(gemm_bulk<3>, cudaFuncAttributeMaxDynamicSharedMemorySize, SMEM_GEMM_);
    cudaFuncSetAttribute(gemm_bulk<2>, cudaFuncAttributeMaxDynamicSharedMemorySize, SMEM_GEMM_);

    prep_scale_kernel<<<1, 128>>>(pds, qs);

    const int tA = MTOK_ * (E_ / 8);
    split_tiled_A<<<(tA + 1023) / 1024, 256>>>(hs, hsh, hsl, MTOK_, MTOK_, E_);
    const int tB = E_ * (E_ / 8);
    split_tiled_B<<<(tB + 1023) / 1024, 256>>>(w_q, wh + 0*(size_t)WELEM_, wl + 0*(size_t)WELEM_, E_, E_);
    split_tiled_B<<<(tB + 1023) / 1024, 256>>>(w_k, wh + 1*(size_t)WELEM_, wl + 1*(size_t)WELEM_, E_, E_);
    split_tiled_B<<<(tB + 1023) / 1024, 256>>>(w_v, wh + 2*(size_t)WELEM_, wl + 2*(size_t)WELEM_, E_, E_);
    split_tiled_B<<<(tB + 1023) / 1024, 256>>>(w_p, wh + 3*(size_t)WELEM_, wl + 3*(size_t)WELEM_, E_, E_);
    split_tiled_B<<<(tB + 1023) / 1024, 256>>>(w_r, wh + 4*(size_t)WELEM_, wl + 4*(size_t)WELEM_, E_, E_);
    const int tPE = 128 * (E_ / 8);
    split_tiled_A<<<(tPE + 1023) / 1024, 256>>>(pe, peh, pel, CTX_, 128, E_);

    const dim3 gBig(E_ / 256, MTOK_ / 128);   // (6, 192)
    gemm_bulk<3><<<gBig, 256, SMEM_GEMM_>>>(hsh, hsl, wh + 0*(size_t)WELEM_, wl + 0*(size_t)WELEM_,
                                            q, MTOK_, E_, E_, 1, qs, 1.f);
    gemm_bulk<3><<<gBig, 256, SMEM_GEMM_>>>(hsh, hsl, wh + 1*(size_t)WELEM_, wl + 1*(size_t)WELEM_,
                                            k, MTOK_, E_, E_, 2, nullptr, KSCALE);
    gemm_bulk<2><<<gBig, 256, SMEM_GEMM_>>>(hsh, hsl, wh + 2*(size_t)WELEM_, wl + 2*(size_t)WELEM_,
                                            v, MTOK_, E_, E_, 0, nullptr, 1.f);
    gemm_bulk<3><<<dim3(E_ / 256, 1), 256, SMEM_GEMM_>>>(peh, pel, wh + 4*(size_t)WELEM_, wl + 4*(size_t)WELEM_,
                                            rk, CTX_, E_, E_, 0, nullptr, 1.f);

    float* attn = ((size_t)out_size >= OUT_MAIN + ATTN_SZ) ? (out + OUT_MAIN) : nullptr;
    attn_kernel<<<dim3(NB_, H_, B_), 384>>>(q, k, v, rk, o, attn);

    split_tiled_A<<<(tA + 1023) / 1024, 256>>>(o, och, ocl, MTOK_, MTOK_, E_);
    gemm_bulk<2><<<gBig, 256, SMEM_GEMM_>>>(och, ocl, wh + 3*(size_t)WELEM_, wl + 3*(size_t)WELEM_,
                                            out, MTOK_, E_, E_, 0, nullptr, 1.f);
}

// round 15
// speedup vs baseline: 1.0900x; 1.0224x over previous
#include <cuda_runtime.h>
#include <cuda_fp16.h>
#include <stdint.h>
#include <math.h>

// ---------------- problem constants ----------------
#define B_    8
#define S_    3072
#define H_    12
#define D_    128
#define E_    1536
#define NB_   256
#define CHUNK_ 12
#define CTX_  24
#define MTOK_ (B_*S_)         // 24576

#define OUT_MAIN  ((size_t)MTOK_ * E_)
#define ATTN_SZ   ((size_t)B_*H_*NB_*CHUNK_*CTX_)
#define WELEM_    (E_*E_)

#define QSCALE_BASE (0.088388347648318447f / 0.69314718055994531f)
#define KSCALE      (1.3132616875182228f  / 0.69314718055994531f)

// ---------------- scratch (device globals) ----------------
__device__ float g_q[OUT_MAIN];
__device__ float g_k[OUT_MAIN];
__device__ float g_v[OUT_MAIN];
__device__ float g_o[OUT_MAIN];
__device__ float g_relk[CTX_ * E_];
__device__ float g_qdscale[D_];

// tiled+swizzled fp16 hi/lo operand storage
__device__ __half g_hs_hi[OUT_MAIN];
__device__ __half g_hs_lo[OUT_MAIN];
__device__ __half g_oc_hi[OUT_MAIN];
__device__ __half g_oc_lo[OUT_MAIN];
__device__ __half g_w_hi[5][WELEM_];
__device__ __half g_w_lo[5][WELEM_];
__device__ __half g_pe_hi[128 * E_];
__device__ __half g_pe_lo[128 * E_];

// ---------------- helpers ----------------
__device__ __forceinline__ void mma_f16(float c[4], unsigned a0, unsigned a1,
                                        unsigned a2, unsigned a3,
                                        unsigned b0, unsigned b1){
    asm volatile(
        "mma.sync.aligned.m16n8k16.row.col.f32.f16.f16.f32 "
        "{%0,%1,%2,%3}, {%4,%5,%6,%7}, {%8,%9}, {%0,%1,%2,%3};"
        : "+f"(c[0]), "+f"(c[1]), "+f"(c[2]), "+f"(c[3])
        : "r"(a0), "r"(a1), "r"(a2), "r"(a3), "r"(b0), "r"(b1));
}
__device__ __forceinline__ void ldsm4(unsigned r[4], unsigned addr){
    asm volatile("ldmatrix.sync.aligned.m8n8.x4.shared.b16 {%0,%1,%2,%3}, [%4];"
                 : "=r"(r[0]), "=r"(r[1]), "=r"(r[2]), "=r"(r[3]) : "r"(addr));
}
__device__ __forceinline__ void bulk_cp(unsigned dst, const void* src, unsigned bytes,
                                        unsigned mbar){
    asm volatile(
        "cp.async.bulk.shared::cluster.global.mbarrier::complete_tx::bytes "
        "[%0], [%1], %2, [%3];"
        :: "r"(dst), "l"(src), "r"(bytes), "r"(mbar) : "memory");
}
#define MBAR_INIT(addr, cnt) \
    asm volatile("mbarrier.init.shared.b64 [%0], %1;" :: "r"(addr), "r"(cnt) : "memory")
#define MBAR_EXPECT_TX(addr, bytes) \
    asm volatile("mbarrier.arrive.expect_tx.shared.b64 _, [%0], %1;" \
                 :: "r"(addr), "r"(bytes) : "memory")
#define MBAR_WAIT(mbar, parity) do {                                        \
    asm volatile(                                                           \
        "{\n\t.reg .pred P1;\n\t"                                           \
        "WL_%=:\n\t"                                                        \
        "mbarrier.try_wait.parity.acquire.cta.shared::cta.b64 P1, [%0], %1, 0x989680;\n\t" \
        "@P1 bra.uni WD_%=;\n\t"                                            \
        "bra.uni WL_%=;\n\t"                                                \
        "WD_%=:\n\t}"                                                       \
        :: "r"(mbar), "r"(parity) : "memory");                              \
} while (0)

// ---------------- fp32 -> fp16 hi/lo split into tiled+swizzled layout -------
__device__ __forceinline__ unsigned pack2hi(float a, float b){
    __half2 t = __halves2half2(__float2half_rn(a), __float2half_rn(b));
    return *(unsigned*)&t;
}
__device__ __forceinline__ unsigned pack2lo(float a, float b){
    float ha = __half2float(__float2half_rn(a));
    float hb = __half2float(__float2half_rn(b));
    __half2 t = __halves2half2(__float2half_rn(a - ha), __float2half_rn(b - hb));
    return *(unsigned*)&t;
}

// A-type: 128-row tiles of 128B rows (64 halves), SW128 swizzled, 16KB/tile
__global__ void split_tiled_A(const float* __restrict__ src,
                              __half* __restrict__ hi,
                              __half* __restrict__ lo,
                              int Mvalid, int Mpad, int K)
{
    const int id = blockIdx.x * 256 + threadIdx.x;
    const int CK = K >> 3;
    if (id >= Mpad * CK) return;
    const int m = id / CK, c = id % CK;
    float4 x0 = make_float4(0.f,0.f,0.f,0.f), x1 = x0;
    if (m < Mvalid) {
        const float4* s = (const float4*)(src + (size_t)m * K + c * 8);
        x0 = s[0]; x1 = s[1];
    }
    const size_t tile = (size_t)(m >> 7) * (K >> 6) + (c >> 3);
    const unsigned inner = (unsigned)((m & 127) * 128 + (((c & 7) * 16) ^ ((m & 7) * 16)));
    uint4 h = make_uint4(pack2hi(x0.x,x0.y), pack2hi(x0.z,x0.w),
                         pack2hi(x1.x,x1.y), pack2hi(x1.z,x1.w));
    uint4 l = make_uint4(pack2lo(x0.x,x0.y), pack2lo(x0.z,x0.w),
                         pack2lo(x1.x,x1.y), pack2lo(x1.z,x1.w));
    *(uint4*)((char*)hi + tile * 16384 + inner) = h;
    *(uint4*)((char*)lo + tile * 16384 + inner) = l;
}

// B-type split for all 5 weights in ONE launch: grid.y selects the weight.
__global__ void split_tiled_W(const float* __restrict__ s0, const float* __restrict__ s1,
                              const float* __restrict__ s2, const float* __restrict__ s3,
                              const float* __restrict__ s4,
                              __half* __restrict__ hiBase, __half* __restrict__ loBase)
{
    const int w = blockIdx.y;
    const float* src = (w == 0) ? s0 : (w == 1) ? s1 : (w == 2) ? s2 : (w == 3) ? s3 : s4;
    __half* hi = hiBase + (size_t)w * WELEM_;
    __half* lo = loBase + (size_t)w * WELEM_;

    const int id = blockIdx.x * 256 + threadIdx.x;
    const int CK = E_ >> 3;
    if (id >= E_ * CK) return;
    const int n = id / CK, c = id % CK;
    const float4* s = (const float4*)(src + (size_t)n * E_ + c * 8);
    float4 x0 = s[0], x1 = s[1];
    const size_t tile = (size_t)(n >> 8) * (E_ >> 6) + (c >> 3);
    const unsigned inner = (unsigned)((n & 255) * 128 + (((c & 7) * 16) ^ ((n & 7) * 16)));
    uint4 h = make_uint4(pack2hi(x0.x,x0.y), pack2hi(x0.z,x0.w),
                         pack2hi(x1.x,x1.y), pack2hi(x1.z,x1.w));
    uint4 l = make_uint4(pack2lo(x0.x,x0.y), pack2lo(x0.z,x0.w),
                         pack2lo(x1.x,x1.y), pack2lo(x1.z,x1.w));
    *(uint4*)((char*)hi + tile * 32768 + inner) = h;
    *(uint4*)((char*)lo + tile * 32768 + inner) = l;
}

__global__ void prep_scale_kernel(const float* __restrict__ pds, float* __restrict__ out)
{
    int d = threadIdx.x;
    if (d < D_) {
        float x = pds[d];
        float sp = (x > 20.f) ? x : log1pf(expf(x));
        out[d] = QSCALE_BASE * sp;
    }
}

// ============================================================================
// fp16 hi/lo tensor-core NT GEMM with cp.async.bulk tile loads.
// 128x256 CTA tile, 256 threads, warp tile 64x64, BK=64 halves,
// 2-stage mbarrier pipeline, m16n8k16 f16.
// NPASS=3: Ah*Bh + Al*Bh + Ah*Bl.  NPASS=2: Ah*Bh + Al*Bh (=A*Bh).
// mode: 0 plain f32; 1 colscale f32; 2 const-scale f32.
// Piggyback: if A2h != null, grid-y row (gridDim.y-1) computes the secondary
// problem C2[M2,N] = A2 * B2^T (mode 0) — all of A, B, C, M swapped.
// ============================================================================
#define TILEA_B  16384
#define TILEB_B  32768
#define STB_     (2*TILEA_B + 2*TILEB_B)   // 98304 per stage
#define SMEM_GEMM_ (2*STB_ + 128)          // 196736

#define SOFF_AH_ 0
#define SOFF_AL_ TILEA_B
#define SOFF_BH_ (2*TILEA_B)
#define SOFF_BL_ (2*TILEA_B + TILEB_B)

template<int NPASS>
__global__ void __launch_bounds__(256)
gemm_bulk(const __half* __restrict__ Aht, const __half* __restrict__ Alt,
          const __half* __restrict__ Bht, const __half* __restrict__ Blt,
          float* __restrict__ C, int M, int N, int K,
          int mode, const float* __restrict__ colscale, float cscale,
          const __half* A2h, const __half* A2l,
          const __half* B2h, const __half* B2l, float* C2, int M2)
{
    extern __shared__ char smem[];
    const unsigned sb = (unsigned)__cvta_generic_to_shared(smem);
    const unsigned mb0 = sb + 2 * STB_;

    const int tid  = threadIdx.x;
    const int lane = tid & 31;
    const int warp = tid >> 5;
    const int wm = warp >> 2;
    const int wn = warp & 3;
    const int lr = lane >> 2;
    const int lc = lane & 3;

    // piggyback dispatch (uniform per CTA)
    int by = blockIdx.y;
    const __half* pAh = Aht; const __half* pAl = Alt;
    const __half* pBh = Bht; const __half* pBl = Blt;
    float* pC = C; int pM = M; int pmode = mode;
    if (A2h != nullptr && by == (int)gridDim.y - 1) {
        pAh = A2h; pAl = A2l; pBh = B2h; pBl = B2l;
        pC = C2; pM = M2; pmode = 0; by = 0;
    }

    const int KT = K >> 6;
    const int aTile = by * KT;
    const int bTile = blockIdx.x * KT;

    if (tid == 0) { MBAR_INIT(mb0, 1); MBAR_INIT(mb0 + 8, 1); }
    __syncthreads();

    float acc[4][8][4];
#pragma unroll
    for (int i = 0; i < 4; i++)
#pragma unroll
        for (int j = 0; j < 8; j++)
#pragma unroll
            for (int r = 0; r < 4; r++) acc[i][j][r] = 0.f;

    const int g  = lane >> 3;
    const int tr = lane & 7;
    unsigned aoff[4], aswz[4];
#pragma unroll
    for (int mt = 0; mt < 4; mt++) {
        const int row = wm * 64 + mt * 16 + (g & 1) * 8 + tr;
        aoff[mt] = (unsigned)(row * 128);
        aswz[mt] = (unsigned)((row & 7) * 16);
    }
    const unsigned alane = (unsigned)((g >> 1) * 16);
    unsigned boff[4], bswz[4];
#pragma unroll
    for (int n2 = 0; n2 < 4; n2++) {
        const int n = wn * 64 + n2 * 16 + (g >> 1) * 8 + tr;
        boff[n2] = (unsigned)(n * 128);
        bswz[n2] = (unsigned)((n & 7) * 16);
    }
    const unsigned blane = (unsigned)((g & 1) * 16);

    const unsigned stage_tx = (NPASS == 3) ? (unsigned)STB_ : (unsigned)(STB_ - TILEB_B);

    auto issue = [&](int it, int s){
        if (tid == 0) {
            const unsigned mb = mb0 + s * 8;
            MBAR_EXPECT_TX(mb, stage_tx);
            const unsigned dst = sb + s * STB_;
            bulk_cp(dst + SOFF_AH_, (const char*)pAh + (size_t)(aTile + it) * TILEA_B, TILEA_B, mb);
            bulk_cp(dst + SOFF_AL_, (const char*)pAl + (size_t)(aTile + it) * TILEA_B, TILEA_B, mb);
            bulk_cp(dst + SOFF_BH_, (const char*)pBh + (size_t)(bTile + it) * TILEB_B, TILEB_B, mb);
            if (NPASS == 3)
                bulk_cp(dst + SOFF_BL_, (const char*)pBl + (size_t)(bTile + it) * TILEB_B, TILEB_B, mb);
        }
    };

    issue(0, 0);
    issue(1, 1);

    for (int it = 0; it < KT; it++) {
        const int s = it & 1;
        MBAR_WAIT(mb0 + s * 8, (unsigned)((it >> 1) & 1));

        const unsigned base = sb + s * STB_;
        const unsigned sAh = base + SOFF_AH_;
        const unsigned sAl = base + SOFF_AL_;
        const unsigned sBh = base + SOFF_BH_;
        const unsigned sBl = base + SOFF_BL_;

#pragma unroll
        for (int k0 = 0; k0 < 4; k0++) {
            const unsigned kb = (unsigned)(k0 * 32);

            unsigned ah[4][4], bh[4][4];
#pragma unroll
            for (int mt = 0; mt < 4; mt++)
                ldsm4(ah[mt], sAh + aoff[mt] + ((kb + alane) ^ aswz[mt]));
#pragma unroll
            for (int n2 = 0; n2 < 4; n2++)
                ldsm4(bh[n2], sBh + boff[n2] + ((kb + blane) ^ bswz[n2]));
#pragma unroll
            for (int mt = 0; mt < 4; mt++)
#pragma unroll
                for (int nt = 0; nt < 8; nt++)
                    mma_f16(acc[mt][nt], ah[mt][0], ah[mt][1], ah[mt][2], ah[mt][3],
                            bh[nt >> 1][(nt & 1) * 2], bh[nt >> 1][(nt & 1) * 2 + 1]);

            unsigned xl[4][4];
#pragma unroll
            for (int mt = 0; mt < 4; mt++)
                ldsm4(xl[mt], sAl + aoff[mt] + ((kb + alane) ^ aswz[mt]));
#pragma unroll
            for (int mt = 0; mt < 4; mt++)
#pragma unroll
                for (int nt = 0; nt < 8; nt++)
                    mma_f16(acc[mt][nt], xl[mt][0], xl[mt][1], xl[mt][2], xl[mt][3],
                            bh[nt >> 1][(nt & 1) * 2], bh[nt >> 1][(nt & 1) * 2 + 1]);

            if (NPASS == 3) {
#pragma unroll
                for (int n2 = 0; n2 < 4; n2++)
                    ldsm4(xl[n2], sBl + boff[n2] + ((kb + blane) ^ bswz[n2]));
#pragma unroll
                for (int mt = 0; mt < 4; mt++)
#pragma unroll
                    for (int nt = 0; nt < 8; nt++)
                        mma_f16(acc[mt][nt], ah[mt][0], ah[mt][1], ah[mt][2], ah[mt][3],
                                xl[nt >> 1][(nt & 1) * 2], xl[nt >> 1][(nt & 1) * 2 + 1]);
            }
        }
        __syncthreads();
        if (it + 2 < KT) issue(it + 2, s);
    }

    // --- epilogue ---
    const int bm = by * 128;
    const int bn = blockIdx.x * 256;
#pragma unroll
    for (int mt = 0; mt < 4; mt++) {
#pragma unroll
        for (int nt = 0; nt < 8; nt++) {
            const int r0 = bm + wm * 64 + mt * 16 + lr;
            const int c0 = bn + wn * 64 + nt * 8 + 2 * lc;
            float v0 = acc[mt][nt][0], v1 = acc[mt][nt][1];
            float v2 = acc[mt][nt][2], v3 = acc[mt][nt][3];
            if (pmode == 1) {
                const float s0 = colscale[c0 & (D_-1)], s1 = colscale[(c0+1) & (D_-1)];
                v0 *= s0; v1 *= s1; v2 *= s0; v3 *= s1;
            } else if (pmode == 2) {
                v0 *= cscale; v1 *= cscale; v2 *= cscale; v3 *= cscale;
            }
            if (r0 < pM)     *(float2*)(pC + (size_t)r0      * N + c0) = make_float2(v0, v1);
            if (r0 + 8 < pM) *(float2*)(pC + (size_t)(r0+8)  * N + c0) = make_float2(v2, v3);
        }
    }
}

// ---------------- chunked local attention (R10 structure) -------------------
__global__ void __launch_bounds__(384)
attn_kernel(const float* __restrict__ q, const float* __restrict__ k,
            const float* __restrict__ v, const float* __restrict__ relk,
            float* __restrict__ o, float* __restrict__ attn_out)
{
    __shared__ float sq[CHUNK_][129];
    __shared__ float sk[CTX_][129];
    __shared__ float sv[CTX_][129];
    __shared__ float sr[CTX_][129];
    __shared__ float sac[CHUNK_][CTX_];
    __shared__ float sbd[CHUNK_][CTX_];
    __shared__ float sw[CHUNK_][25];

    const int n = blockIdx.x, h = blockIdx.y, b = blockIdx.z;
    const int t = threadIdx.x;

    for (int i = t; i < CHUNK_ * D_; i += 384) {
        const int c = i >> 7, d = i & 127;
        const int s = n * CHUNK_ + c;
        sq[c][d] = q[((size_t)(b * S_ + s)) * E_ + h * D_ + d];
    }
    for (int i = t; i < CTX_ * D_; i += 384) {
        const int j = i >> 7, d = i & 127;
        const int s = n * CHUNK_ - 12 + j;
        float kv = 0.f, vv = 0.f;
        if (s >= 0 && s < S_) {
            const size_t base = ((size_t)(b * S_ + s)) * E_ + h * D_ + d;
            kv = k[base]; vv = v[base];
        }
        sk[j][d] = kv;
        sv[j][d] = vv;
        sr[j][d] = relk[(size_t)j * E_ + h * D_ + d];
    }
    __syncthreads();

    for (int i = t; i < CHUNK_ * CTX_; i += 384) {
        const int c = i / CTX_, j = i % CTX_;
        float a = 0.f, bb = 0.f;
#pragma unroll 8
        for (int d = 0; d < D_; d++) {
            const float qq = sq[c][d];
            a  = fmaf(qq, sk[j][d], a);
            bb = fmaf(qq, sr[j][d], bb);
        }
        sac[c][j] = a;
        sbd[c][j] = bb;
    }
    __syncthreads();

    for (int i = t; i < CHUNK_ * CTX_; i += 384) {
        const int c = i / CTX_, j = i % CTX_;
        const int idx = c * CTX_ + j;
        const int r = idx / (CTX_ + 1);
        const int p = idx % (CTX_ + 1);
        const float bd = (p < CTX_) ? sbd[r][p] : 0.f;
        float l = sac[c][j] + bd;
        l = 50.f * tanhf(l * 0.02f);
        sw[c][j] = l;
    }
    __syncthreads();

    if (t < CHUNK_) {
        const int c = t;
        float m = -1e30f;
        for (int j = 0; j < CTX_; j++) m = fmaxf(m, sw[c][j]);
        float sum = 0.f;
        for (int j = 0; j < CTX_; j++) { const float e = expf(sw[c][j] - m); sum += e; sw[c][j] = e; }
        const float inv = 1.f / sum;
        for (int j = 0; j < CTX_; j++) sw[c][j] *= inv;
    }
    __syncthreads();

    if (attn_out) {
        for (int i = t; i < CHUNK_ * CTX_; i += 384) {
            const int c = i / CTX_, j = i % CTX_;
            attn_out[((((size_t)b * H_ + h) * NB_ + n) * CHUNK_ + c) * CTX_ + j] = sw[c][j];
        }
    }

    for (int i = t; i < CHUNK_ * D_; i += 384) {
        const int c = i >> 7, d = i & 127;
        float acc = 0.f;
#pragma unroll
        for (int j = 0; j < CTX_; j++) acc = fmaf(sw[c][j], sv[j][d], acc);
        o[((size_t)(b * S_ + n * CHUNK_ + c)) * E_ + h * D_ + d] = acc;
    }
}

// ---------------- launch -----------------------------------------------------
extern "C" void kernel_launch(void* const* d_in, const int* in_sizes, int n_in,
                              void* d_out, int out_size)
{
    const float* hs   = (const float*)d_in[0];
    const float* pe   = (const float*)d_in[1];
    const float* w_q  = (const float*)d_in[2];
    const float* w_k  = (const float*)d_in[3];
    const float* w_v  = (const float*)d_in[4];
    const float* w_p  = (const float*)d_in[5];
    const float* w_r  = (const float*)d_in[6];
    const float* pds  = (const float*)d_in[7];
    float* out = (float*)d_out;

    float *q, *k, *v, *o, *rk, *qs;
    cudaGetSymbolAddress((void**)&q,  g_q);
    cudaGetSymbolAddress((void**)&k,  g_k);
    cudaGetSymbolAddress((void**)&v,  g_v);
    cudaGetSymbolAddress((void**)&o,  g_o);
    cudaGetSymbolAddress((void**)&rk, g_relk);
    cudaGetSymbolAddress((void**)&qs, g_qdscale);

    __half *hsh, *hsl, *och, *ocl, *wh, *wl, *peh, *pel;
    cudaGetSymbolAddress((void**)&hsh, g_hs_hi);
    cudaGetSymbolAddress((void**)&hsl, g_hs_lo);
    cudaGetSymbolAddress((void**)&och, g_oc_hi);
    cudaGetSymbolAddress((void**)&ocl, g_oc_lo);
    cudaGetSymbolAddress((void**)&wh,  g_w_hi);
    cudaGetSymbolAddress((void**)&wl,  g_w_lo);
    cudaGetSymbolAddress((void**)&peh, g_pe_hi);
    cudaGetSymbolAddress((void**)&pel, g_pe_lo);

    cudaFuncSetAttribute(gemm_bulk<3>, cudaFuncAttributeMaxDynamicSharedMemorySize, SMEM_GEMM_);
    cudaFuncSetAttribute(gemm_bulk<2>, cudaFuncAttributeMaxDynamicSharedMemorySize, SMEM_GEMM_);

    prep_scale_kernel<<<1, 128>>>(pds, qs);

    const int tA = MTOK_ * (E_ / 8);
    split_tiled_A<<<(tA + 255) / 256, 256>>>(hs, hsh, hsl, MTOK_, MTOK_, E_);
    const int tB = E_ * (E_ / 8);
    split_tiled_W<<<dim3((tB + 255) / 256, 5), 256>>>(w_q, w_k, w_v, w_p, w_r, wh, wl);
    const int tPE = 128 * (E_ / 8);
    split_tiled_A<<<(tPE + 255) / 256, 256>>>(pe, peh, pel, CTX_, 128, E_);

    const dim3 gQ(E_ / 256, MTOK_ / 128 + 1);   // (6, 193) — last row = rel GEMM
    const dim3 gBig(E_ / 256, MTOK_ / 128);     // (6, 192)

    // q GEMM + piggybacked rel GEMM (A2=pe tiles, B2=w_r tiles, C2=relk)
    gemm_bulk<3><<<gQ, 256, SMEM_GEMM_>>>(hsh, hsl, wh + 0*(size_t)WELEM_, wl + 0*(size_t)WELEM_,
                                          q, MTOK_, E_, E_, 1, qs, 1.f,
                                          peh, pel,
                                          wh + 4*(size_t)WELEM_, wl + 4*(size_t)WELEM_,
                                          rk, CTX_);
    gemm_bulk<3><<<gBig, 256, SMEM_GEMM_>>>(hsh, hsl, wh + 1*(size_t)WELEM_, wl + 1*(size_t)WELEM_,
                                            k, MTOK_, E_, E_, 2, nullptr, KSCALE,
                                            nullptr, nullptr, nullptr, nullptr, nullptr, 0);
    gemm_bulk<2><<<gBig, 256, SMEM_GEMM_>>>(hsh, hsl, wh + 2*(size_t)WELEM_, wl + 2*(size_t)WELEM_,
                                            v, MTOK_, E_, E_, 0, nullptr, 1.f,
                                            nullptr, nullptr, nullptr, nullptr, nullptr, 0);

    float* attn = ((size_t)out_size >= OUT_MAIN + ATTN_SZ) ? (out + OUT_MAIN) : nullptr;
    attn_kernel<<<dim3(NB_, H_, B_), 384>>>(q, k, v, rk, o, attn);

    split_tiled_A<<<(tA + 255) / 256, 256>>>(o, och, ocl, MTOK_, MTOK_, E_);
    gemm_bulk<2><<<gBig, 256, SMEM_GEMM_>>>(och, ocl, wh + 3*(size_t)WELEM_, wl + 3*(size_t)WELEM_,
                                            out, MTOK_, E_, E_, 0, nullptr, 1.f,
                                            nullptr, nullptr, nullptr, nullptr, nullptr, 0);
}

// round 16
// speedup vs baseline: 1.2633x; 1.1590x over previous
#include <cuda_runtime.h>
#include <cuda_fp16.h>
#include <stdint.h>
#include <math.h>

// ---------------- problem constants ----------------
#define B_    8
#define S_    3072
#define H_    12
#define D_    128
#define E_    1536
#define NB_   256
#define CHUNK_ 12
#define CTX_  24
#define MTOK_ (B_*S_)         // 24576

#define OUT_MAIN  ((size_t)MTOK_ * E_)
#define ATTN_SZ   ((size_t)B_*H_*NB_*CHUNK_*CTX_)
#define WELEM_    (E_*E_)

#define QSCALE_BASE (0.088388347648318447f / 0.69314718055994531f)
#define KSCALE      (1.3132616875182228f  / 0.69314718055994531f)

// ---------------- scratch (device globals) ----------------
__device__ float g_q[OUT_MAIN];
__device__ float g_k[OUT_MAIN];
__device__ float g_v[OUT_MAIN];
__device__ float g_o[OUT_MAIN];
__device__ float g_relk[CTX_ * E_];
__device__ float g_qdscale[D_];

// tiled+swizzled fp16 hi/lo operand storage
__device__ __half g_hs_hi[OUT_MAIN];
__device__ __half g_hs_lo[OUT_MAIN];
__device__ __half g_oc_hi[OUT_MAIN];
__device__ __half g_oc_lo[OUT_MAIN];
__device__ __half g_w_hi[5][WELEM_];
__device__ __half g_w_lo[5][WELEM_];
__device__ __half g_pe_hi[128 * E_];
__device__ __half g_pe_lo[128 * E_];

// ---------------- helpers ----------------
__device__ __forceinline__ void mma_f16(float c[4], unsigned a0, unsigned a1,
                                        unsigned a2, unsigned a3,
                                        unsigned b0, unsigned b1){
    asm volatile(
        "mma.sync.aligned.m16n8k16.row.col.f32.f16.f16.f32 "
        "{%0,%1,%2,%3}, {%4,%5,%6,%7}, {%8,%9}, {%0,%1,%2,%3};"
        : "+f"(c[0]), "+f"(c[1]), "+f"(c[2]), "+f"(c[3])
        : "r"(a0), "r"(a1), "r"(a2), "r"(a3), "r"(b0), "r"(b1));
}
__device__ __forceinline__ void ldsm4(unsigned r[4], unsigned addr){
    asm volatile("ldmatrix.sync.aligned.m8n8.x4.shared.b16 {%0,%1,%2,%3}, [%4];"
                 : "=r"(r[0]), "=r"(r[1]), "=r"(r[2]), "=r"(r[3]) : "r"(addr));
}
__device__ __forceinline__ void bulk_cp(unsigned dst, const void* src, unsigned bytes,
                                        unsigned mbar){
    asm volatile(
        "cp.async.bulk.shared::cluster.global.mbarrier::complete_tx::bytes "
        "[%0], [%1], %2, [%3];"
        :: "r"(dst), "l"(src), "r"(bytes), "r"(mbar) : "memory");
}
#define MBAR_INIT(addr, cnt) \
    asm volatile("mbarrier.init.shared.b64 [%0], %1;" :: "r"(addr), "r"(cnt) : "memory")
#define MBAR_EXPECT_TX(addr, bytes) \
    asm volatile("mbarrier.arrive.expect_tx.shared.b64 _, [%0], %1;" \
                 :: "r"(addr), "r"(bytes) : "memory")
#define MBAR_WAIT(mbar, parity) do {                                        \
    asm volatile(                                                           \
        "{\n\t.reg .pred P1;\n\t"                                           \
        "WL_%=:\n\t"                                                        \
        "mbarrier.try_wait.parity.acquire.cta.shared::cta.b64 P1, [%0], %1, 0x989680;\n\t" \
        "@P1 bra.uni WD_%=;\n\t"                                            \
        "bra.uni WL_%=;\n\t"                                                \
        "WD_%=:\n\t}"                                                       \
        :: "r"(mbar), "r"(parity) : "memory");                              \
} while (0)

// ---------------- fp32 -> fp16 hi/lo split into tiled+swizzled layout -------
__device__ __forceinline__ unsigned pack2hi(float a, float b){
    __half2 t = __halves2half2(__float2half_rn(a), __float2half_rn(b));
    return *(unsigned*)&t;
}
__device__ __forceinline__ unsigned pack2lo(float a, float b){
    float ha = __half2float(__float2half_rn(a));
    float hb = __half2float(__float2half_rn(b));
    __half2 t = __halves2half2(__float2half_rn(a - ha), __float2half_rn(b - hb));
    return *(unsigned*)&t;
}

// A-type: 128-row tiles of 128B rows (64 halves), SW128 swizzled, 16KB/tile.
// WLO=false skips the lo buffer (for 1-pass consumers).
template<bool WLO>
__global__ void split_tiled_A(const float* __restrict__ src,
                              __half* __restrict__ hi,
                              __half* __restrict__ lo,
                              int Mvalid, int Mpad, int K)
{
    const int id = blockIdx.x * 256 + threadIdx.x;
    const int CK = K >> 3;
    if (id >= Mpad * CK) return;
    const int m = id / CK, c = id % CK;
    float4 x0 = make_float4(0.f,0.f,0.f,0.f), x1 = x0;
    if (m < Mvalid) {
        const float4* s = (const float4*)(src + (size_t)m * K + c * 8);
        x0 = s[0]; x1 = s[1];
    }
    const size_t tile = (size_t)(m >> 7) * (K >> 6) + (c >> 3);
    const unsigned inner = (unsigned)((m & 127) * 128 + (((c & 7) * 16) ^ ((m & 7) * 16)));
    uint4 h = make_uint4(pack2hi(x0.x,x0.y), pack2hi(x0.z,x0.w),
                         pack2hi(x1.x,x1.y), pack2hi(x1.z,x1.w));
    *(uint4*)((char*)hi + tile * 16384 + inner) = h;
    if (WLO) {
        uint4 l = make_uint4(pack2lo(x0.x,x0.y), pack2lo(x0.z,x0.w),
                             pack2lo(x1.x,x1.y), pack2lo(x1.z,x1.w));
        *(uint4*)((char*)lo + tile * 16384 + inner) = l;
    }
}

// B-type split for all 5 weights in ONE launch: grid.y selects the weight.
__global__ void split_tiled_W(const float* __restrict__ s0, const float* __restrict__ s1,
                              const float* __restrict__ s2, const float* __restrict__ s3,
                              const float* __restrict__ s4,
                              __half* __restrict__ hiBase, __half* __restrict__ loBase)
{
    const int w = blockIdx.y;
    const float* src = (w == 0) ? s0 : (w == 1) ? s1 : (w == 2) ? s2 : (w == 3) ? s3 : s4;
    __half* hi = hiBase + (size_t)w * WELEM_;
    __half* lo = loBase + (size_t)w * WELEM_;

    const int id = blockIdx.x * 256 + threadIdx.x;
    const int CK = E_ >> 3;
    if (id >= E_ * CK) return;
    const int n = id / CK, c = id % CK;
    const float4* s = (const float4*)(src + (size_t)n * E_ + c * 8);
    float4 x0 = s[0], x1 = s[1];
    const size_t tile = (size_t)(n >> 8) * (E_ >> 6) + (c >> 3);
    const unsigned inner = (unsigned)((n & 255) * 128 + (((c & 7) * 16) ^ ((n & 7) * 16)));
    uint4 h = make_uint4(pack2hi(x0.x,x0.y), pack2hi(x0.z,x0.w),
                         pack2hi(x1.x,x1.y), pack2hi(x1.z,x1.w));
    uint4 l = make_uint4(pack2lo(x0.x,x0.y), pack2lo(x0.z,x0.w),
                         pack2lo(x1.x,x1.y), pack2lo(x1.z,x1.w));
    *(uint4*)((char*)hi + tile * 32768 + inner) = h;
    *(uint4*)((char*)lo + tile * 32768 + inner) = l;
}

__global__ void prep_scale_kernel(const float* __restrict__ pds, float* __restrict__ out)
{
    int d = threadIdx.x;
    if (d < D_) {
        float x = pds[d];
        float sp = (x > 20.f) ? x : log1pf(expf(x));
        out[d] = QSCALE_BASE * sp;
    }
}

// ============================================================================
// fp16 hi/lo tensor-core NT GEMM with cp.async.bulk tile loads.
// 128x256 CTA tile, 256 threads, warp tile 64x64, BK=64 halves,
// 2-stage mbarrier pipeline, m16n8k16 f16.
// NPASS=3: Ah*Bh + Al*Bh + Ah*Bl.  NPASS=2: Ah*Bh + Al*Bh.  NPASS=1: Ah*Bh.
// mode: 0 plain f32; 1 colscale f32; 2 const-scale f32.
// Piggyback: if A2h != null, grid-y row (gridDim.y-1) computes the secondary
// problem C2[M2,N] = A2 * B2^T (mode 0) — all of A, B, C, M swapped.
// ============================================================================
#define TILEA_B  16384
#define TILEB_B  32768
#define STB_     (2*TILEA_B + 2*TILEB_B)   // 98304 per stage
#define SMEM_GEMM_ (2*STB_ + 128)          // 196736

#define SOFF_AH_ 0
#define SOFF_AL_ TILEA_B
#define SOFF_BH_ (2*TILEA_B)
#define SOFF_BL_ (2*TILEA_B + TILEB_B)

template<int NPASS>
__global__ void __launch_bounds__(256)
gemm_bulk(const __half* __restrict__ Aht, const __half* __restrict__ Alt,
          const __half* __restrict__ Bht, const __half* __restrict__ Blt,
          float* __restrict__ C, int M, int N, int K,
          int mode, const float* __restrict__ colscale, float cscale,
          const __half* A2h, const __half* A2l,
          const __half* B2h, const __half* B2l, float* C2, int M2)
{
    extern __shared__ char smem[];
    const unsigned sb = (unsigned)__cvta_generic_to_shared(smem);
    const unsigned mb0 = sb + 2 * STB_;

    const int tid  = threadIdx.x;
    const int lane = tid & 31;
    const int warp = tid >> 5;
    const int wm = warp >> 2;
    const int wn = warp & 3;
    const int lr = lane >> 2;
    const int lc = lane & 3;

    // piggyback dispatch (uniform per CTA)
    int by = blockIdx.y;
    const __half* pAh = Aht; const __half* pAl = Alt;
    const __half* pBh = Bht; const __half* pBl = Blt;
    float* pC = C; int pM = M; int pmode = mode;
    if (A2h != nullptr && by == (int)gridDim.y - 1) {
        pAh = A2h; pAl = A2l; pBh = B2h; pBl = B2l;
        pC = C2; pM = M2; pmode = 0; by = 0;
    }

    const int KT = K >> 6;
    const int aTile = by * KT;
    const int bTile = blockIdx.x * KT;

    if (tid == 0) { MBAR_INIT(mb0, 1); MBAR_INIT(mb0 + 8, 1); }
    __syncthreads();

    float acc[4][8][4];
#pragma unroll
    for (int i = 0; i < 4; i++)
#pragma unroll
        for (int j = 0; j < 8; j++)
#pragma unroll
            for (int r = 0; r < 4; r++) acc[i][j][r] = 0.f;

    const int g  = lane >> 3;
    const int tr = lane & 7;
    unsigned aoff[4], aswz[4];
#pragma unroll
    for (int mt = 0; mt < 4; mt++) {
        const int row = wm * 64 + mt * 16 + (g & 1) * 8 + tr;
        aoff[mt] = (unsigned)(row * 128);
        aswz[mt] = (unsigned)((row & 7) * 16);
    }
    const unsigned alane = (unsigned)((g >> 1) * 16);
    unsigned boff[4], bswz[4];
#pragma unroll
    for (int n2 = 0; n2 < 4; n2++) {
        const int n = wn * 64 + n2 * 16 + (g >> 1) * 8 + tr;
        boff[n2] = (unsigned)(n * 128);
        bswz[n2] = (unsigned)((n & 7) * 16);
    }
    const unsigned blane = (unsigned)((g & 1) * 16);

    const unsigned stage_tx =
        (NPASS == 3) ? (unsigned)STB_ :
        (NPASS == 2) ? (unsigned)(STB_ - TILEB_B) :
                       (unsigned)(TILEA_B + TILEB_B);

    auto issue = [&](int it, int s){
        if (tid == 0) {
            const unsigned mb = mb0 + s * 8;
            MBAR_EXPECT_TX(mb, stage_tx);
            const unsigned dst = sb + s * STB_;
            bulk_cp(dst + SOFF_AH_, (const char*)pAh + (size_t)(aTile + it) * TILEA_B, TILEA_B, mb);
            if (NPASS >= 2)
                bulk_cp(dst + SOFF_AL_, (const char*)pAl + (size_t)(aTile + it) * TILEA_B, TILEA_B, mb);
            bulk_cp(dst + SOFF_BH_, (const char*)pBh + (size_t)(bTile + it) * TILEB_B, TILEB_B, mb);
            if (NPASS == 3)
                bulk_cp(dst + SOFF_BL_, (const char*)pBl + (size_t)(bTile + it) * TILEB_B, TILEB_B, mb);
        }
    };

    issue(0, 0);
    issue(1, 1);

    for (int it = 0; it < KT; it++) {
        const int s = it & 1;
        MBAR_WAIT(mb0 + s * 8, (unsigned)((it >> 1) & 1));

        const unsigned base = sb + s * STB_;
        const unsigned sAh = base + SOFF_AH_;
        const unsigned sAl = base + SOFF_AL_;
        const unsigned sBh = base + SOFF_BH_;
        const unsigned sBl = base + SOFF_BL_;

#pragma unroll
        for (int k0 = 0; k0 < 4; k0++) {
            const unsigned kb = (unsigned)(k0 * 32);

            unsigned ah[4][4], bh[4][4];
#pragma unroll
            for (int mt = 0; mt < 4; mt++)
                ldsm4(ah[mt], sAh + aoff[mt] + ((kb + alane) ^ aswz[mt]));
#pragma unroll
            for (int n2 = 0; n2 < 4; n2++)
                ldsm4(bh[n2], sBh + boff[n2] + ((kb + blane) ^ bswz[n2]));
#pragma unroll
            for (int mt = 0; mt < 4; mt++)
#pragma unroll
                for (int nt = 0; nt < 8; nt++)
                    mma_f16(acc[mt][nt], ah[mt][0], ah[mt][1], ah[mt][2], ah[mt][3],
                            bh[nt >> 1][(nt & 1) * 2], bh[nt >> 1][(nt & 1) * 2 + 1]);

            if (NPASS >= 2) {
                unsigned xl[4][4];
#pragma unroll
                for (int mt = 0; mt < 4; mt++)
                    ldsm4(xl[mt], sAl + aoff[mt] + ((kb + alane) ^ aswz[mt]));
#pragma unroll
                for (int mt = 0; mt < 4; mt++)
#pragma unroll
                    for (int nt = 0; nt < 8; nt++)
                        mma_f16(acc[mt][nt], xl[mt][0], xl[mt][1], xl[mt][2], xl[mt][3],
                                bh[nt >> 1][(nt & 1) * 2], bh[nt >> 1][(nt & 1) * 2 + 1]);

                if (NPASS == 3) {
#pragma unroll
                    for (int n2 = 0; n2 < 4; n2++)
                        ldsm4(xl[n2], sBl + boff[n2] + ((kb + blane) ^ bswz[n2]));
#pragma unroll
                    for (int mt = 0; mt < 4; mt++)
#pragma unroll
                        for (int nt = 0; nt < 8; nt++)
                            mma_f16(acc[mt][nt], ah[mt][0], ah[mt][1], ah[mt][2], ah[mt][3],
                                    xl[nt >> 1][(nt & 1) * 2], xl[nt >> 1][(nt & 1) * 2 + 1]);
                }
            }
        }
        __syncthreads();
        if (it + 2 < KT) issue(it + 2, s);
    }

    // --- epilogue ---
    const int bm = by * 128;
    const int bn = blockIdx.x * 256;
#pragma unroll
    for (int mt = 0; mt < 4; mt++) {
#pragma unroll
        for (int nt = 0; nt < 8; nt++) {
            const int r0 = bm + wm * 64 + mt * 16 + lr;
            const int c0 = bn + wn * 64 + nt * 8 + 2 * lc;
            float v0 = acc[mt][nt][0], v1 = acc[mt][nt][1];
            float v2 = acc[mt][nt][2], v3 = acc[mt][nt][3];
            if (pmode == 1) {
                const float s0 = colscale[c0 & (D_-1)], s1 = colscale[(c0+1) & (D_-1)];
                v0 *= s0; v1 *= s1; v2 *= s0; v3 *= s1;
            } else if (pmode == 2) {
                v0 *= cscale; v1 *= cscale; v2 *= cscale; v3 *= cscale;
            }
            if (r0 < pM)     *(float2*)(pC + (size_t)r0      * N + c0) = make_float2(v0, v1);
            if (r0 + 8 < pM) *(float2*)(pC + (size_t)(r0+8)  * N + c0) = make_float2(v2, v3);
        }
    }
}

// ---------------- chunked local attention (R10 structure) -------------------
__global__ void __launch_bounds__(384)
attn_kernel(const float* __restrict__ q, const float* __restrict__ k,
            const float* __restrict__ v, const float* __restrict__ relk,
            float* __restrict__ o, float* __restrict__ attn_out)
{
    __shared__ float sq[CHUNK_][129];
    __shared__ float sk[CTX_][129];
    __shared__ float sv[CTX_][129];
    __shared__ float sr[CTX_][129];
    __shared__ float sac[CHUNK_][CTX_];
    __shared__ float sbd[CHUNK_][CTX_];
    __shared__ float sw[CHUNK_][25];

    const int n = blockIdx.x, h = blockIdx.y, b = blockIdx.z;
    const int t = threadIdx.x;

    for (int i = t; i < CHUNK_ * D_; i += 384) {
        const int c = i >> 7, d = i & 127;
        const int s = n * CHUNK_ + c;
        sq[c][d] = q[((size_t)(b * S_ + s)) * E_ + h * D_ + d];
    }
    for (int i = t; i < CTX_ * D_; i += 384) {
        const int j = i >> 7, d = i & 127;
        const int s = n * CHUNK_ - 12 + j;
        float kv = 0.f, vv = 0.f;
        if (s >= 0 && s < S_) {
            const size_t base = ((size_t)(b * S_ + s)) * E_ + h * D_ + d;
            kv = k[base]; vv = v[base];
        }
        sk[j][d] = kv;
        sv[j][d] = vv;
        sr[j][d] = relk[(size_t)j * E_ + h * D_ + d];
    }
    __syncthreads();

    for (int i = t; i < CHUNK_ * CTX_; i += 384) {
        const int c = i / CTX_, j = i % CTX_;
        float a = 0.f, bb = 0.f;
#pragma unroll 8
        for (int d = 0; d < D_; d++) {
            const float qq = sq[c][d];
            a  = fmaf(qq, sk[j][d], a);
            bb = fmaf(qq, sr[j][d], bb);
        }
        sac[c][j] = a;
        sbd[c][j] = bb;
    }
    __syncthreads();

    for (int i = t; i < CHUNK_ * CTX_; i += 384) {
        const int c = i / CTX_, j = i % CTX_;
        const int idx = c * CTX_ + j;
        const int r = idx / (CTX_ + 1);
        const int p = idx % (CTX_ + 1);
        const float bd = (p < CTX_) ? sbd[r][p] : 0.f;
        float l = sac[c][j] + bd;
        l = 50.f * tanhf(l * 0.02f);
        sw[c][j] = l;
    }
    __syncthreads();

    if (t < CHUNK_) {
        const int c = t;
        float m = -1e30f;
        for (int j = 0; j < CTX_; j++) m = fmaxf(m, sw[c][j]);
        float sum = 0.f;
        for (int j = 0; j < CTX_; j++) { const float e = expf(sw[c][j] - m); sum += e; sw[c][j] = e; }
        const float inv = 1.f / sum;
        for (int j = 0; j < CTX_; j++) sw[c][j] *= inv;
    }
    __syncthreads();

    if (attn_out) {
        for (int i = t; i < CHUNK_ * CTX_; i += 384) {
            const int c = i / CTX_, j = i % CTX_;
            attn_out[((((size_t)b * H_ + h) * NB_ + n) * CHUNK_ + c) * CTX_ + j] = sw[c][j];
        }
    }

    for (int i = t; i < CHUNK_ * D_; i += 384) {
        const int c = i >> 7, d = i & 127;
        float acc = 0.f;
#pragma unroll
        for (int j = 0; j < CTX_; j++) acc = fmaf(sw[c][j], sv[j][d], acc);
        o[((size_t)(b * S_ + n * CHUNK_ + c)) * E_ + h * D_ + d] = acc;
    }
}

// ---------------- launch -----------------------------------------------------
extern "C" void kernel_launch(void* const* d_in, const int* in_sizes, int n_in,
                              void* d_out, int out_size)
{
    const float* hs   = (const float*)d_in[0];
    const float* pe   = (const float*)d_in[1];
    const float* w_q  = (const float*)d_in[2];
    const float* w_k  = (const float*)d_in[3];
    const float* w_v  = (const float*)d_in[4];
    const float* w_p  = (const float*)d_in[5];
    const float* w_r  = (const float*)d_in[6];
    const float* pds  = (const float*)d_in[7];
    float* out = (float*)d_out;

    float *q, *k, *v, *o, *rk, *qs;
    cudaGetSymbolAddress((void**)&q,  g_q);
    cudaGetSymbolAddress((void**)&k,  g_k);
    cudaGetSymbolAddress((void**)&v,  g_v);
    cudaGetSymbolAddress((void**)&o,  g_o);
    cudaGetSymbolAddress((void**)&rk, g_relk);
    cudaGetSymbolAddress((void**)&qs, g_qdscale);

    __half *hsh, *hsl, *och, *ocl, *wh, *wl, *peh, *pel;
    cudaGetSymbolAddress((void**)&hsh, g_hs_hi);
    cudaGetSymbolAddress((void**)&hsl, g_hs_lo);
    cudaGetSymbolAddress((void**)&och, g_oc_hi);
    cudaGetSymbolAddress((void**)&ocl, g_oc_lo);
    cudaGetSymbolAddress((void**)&wh,  g_w_hi);
    cudaGetSymbolAddress((void**)&wl,  g_w_lo);
    cudaGetSymbolAddress((void**)&peh, g_pe_hi);
    cudaGetSymbolAddress((void**)&pel, g_pe_lo);

    cudaFuncSetAttribute(gemm_bulk<3>, cudaFuncAttributeMaxDynamicSharedMemorySize, SMEM_GEMM_);
    cudaFuncSetAttribute(gemm_bulk<2>, cudaFuncAttributeMaxDynamicSharedMemorySize, SMEM_GEMM_);
    cudaFuncSetAttribute(gemm_bulk<1>, cudaFuncAttributeMaxDynamicSharedMemorySize, SMEM_GEMM_);

    prep_scale_kernel<<<1, 128>>>(pds, qs);

    const int tA = MTOK_ * (E_ / 8);
    split_tiled_A<true><<<(tA + 255) / 256, 256>>>(hs, hsh, hsl, MTOK_, MTOK_, E_);
    const int tB = E_ * (E_ / 8);
    split_tiled_W<<<dim3((tB + 255) / 256, 5), 256>>>(w_q, w_k, w_v, w_p, w_r, wh, wl);
    const int tPE = 128 * (E_ / 8);
    split_tiled_A<true><<<(tPE + 255) / 256, 256>>>(pe, peh, pel, CTX_, 128, E_);

    const dim3 gQ(E_ / 256, MTOK_ / 128 + 1);   // (6, 193) — last row = rel GEMM
    const dim3 gBig(E_ / 256, MTOK_ / 128);     // (6, 192)

    // q GEMM + piggybacked rel GEMM (A2=pe tiles, B2=w_r tiles, C2=relk)
    gemm_bulk<3><<<gQ, 256, SMEM_GEMM_>>>(hsh, hsl, wh + 0*(size_t)WELEM_, wl + 0*(size_t)WELEM_,
                                          q, MTOK_, E_, E_, 1, qs, 1.f,
                                          peh, pel,
                                          wh + 4*(size_t)WELEM_, wl + 4*(size_t)WELEM_,
                                          rk, CTX_);
    gemm_bulk<3><<<gBig, 256, SMEM_GEMM_>>>(hsh, hsl, wh + 1*(size_t)WELEM_, wl + 1*(size_t)WELEM_,
                                            k, MTOK_, E_, E_, 2, nullptr, KSCALE,
                                            nullptr, nullptr, nullptr, nullptr, nullptr, 0);
    gemm_bulk<1><<<gBig, 256, SMEM_GEMM_>>>(hsh, hsl, wh + 2*(size_t)WELEM_, wl + 2*(size_t)WELEM_,
                                            v, MTOK_, E_, E_, 0, nullptr, 1.f,
                                            nullptr, nullptr, nullptr, nullptr, nullptr, 0);

    float* attn = ((size_t)out_size >= OUT_MAIN + ATTN_SZ) ? (out + OUT_MAIN) : nullptr;
    attn_kernel<<<dim3(NB_, H_, B_), 384>>>(q, k, v, rk, o, attn);

    split_tiled_A<false><<<(tA + 255) / 256, 256>>>(o, och, ocl, MTOK_, MTOK_, E_);
    gemm_bulk<1><<<gBig, 256, SMEM_GEMM_>>>(och, ocl, wh + 3*(size_t)WELEM_, wl + 3*(size_t)WELEM_,
                                            out, MTOK_, E_, E_, 0, nullptr, 1.f,
                                            nullptr, nullptr, nullptr, nullptr, nullptr, 0);
}

// round 17
// speedup vs baseline: 1.3723x; 1.0863x over previous
#include <cuda_runtime.h>
#include <cuda_fp16.h>
#include <stdint.h>
#include <math.h>

// ---------------- problem constants ----------------
#define B_    8
#define S_    3072
#define H_    12
#define D_    128
#define E_    1536
#define NB_   256
#define CHUNK_ 12
#define CTX_  24
#define MTOK_ (B_*S_)         // 24576

#define OUT_MAIN  ((size_t)MTOK_ * E_)
#define ATTN_SZ   ((size_t)B_*H_*NB_*CHUNK_*CTX_)
#define WELEM_    (E_*E_)

#define QSCALE_BASE (0.088388347648318447f / 0.69314718055994531f)
#define KSCALE      (1.3132616875182228f  / 0.69314718055994531f)

// ---------------- scratch (device globals) ----------------
__device__ float g_q[OUT_MAIN];
__device__ float g_k[OUT_MAIN];
__device__ float g_v[OUT_MAIN];
__device__ float g_o[OUT_MAIN];
__device__ float g_relk[CTX_ * E_];
__device__ float g_qdscale[D_];

// tiled+swizzled fp16 hi/lo operand storage
__device__ __half g_hs_hi[OUT_MAIN];
__device__ __half g_hs_lo[OUT_MAIN];
__device__ __half g_oc_hi[OUT_MAIN];
__device__ __half g_oc_lo[OUT_MAIN];
__device__ __half g_w_hi[5][WELEM_];
__device__ __half g_w_lo[5][WELEM_];
__device__ __half g_pe_hi[128 * E_];
__device__ __half g_pe_lo[128 * E_];

// ---------------- helpers ----------------
__device__ __forceinline__ void mma_f16(float c[4], unsigned a0, unsigned a1,
                                        unsigned a2, unsigned a3,
                                        unsigned b0, unsigned b1){
    asm volatile(
        "mma.sync.aligned.m16n8k16.row.col.f32.f16.f16.f32 "
        "{%0,%1,%2,%3}, {%4,%5,%6,%7}, {%8,%9}, {%0,%1,%2,%3};"
        : "+f"(c[0]), "+f"(c[1]), "+f"(c[2]), "+f"(c[3])
        : "r"(a0), "r"(a1), "r"(a2), "r"(a3), "r"(b0), "r"(b1));
}
__device__ __forceinline__ void ldsm4(unsigned r[4], unsigned addr){
    asm volatile("ldmatrix.sync.aligned.m8n8.x4.shared.b16 {%0,%1,%2,%3}, [%4];"
                 : "=r"(r[0]), "=r"(r[1]), "=r"(r[2]), "=r"(r[3]) : "r"(addr));
}
__device__ __forceinline__ void bulk_cp(unsigned dst, const void* src, unsigned bytes,
                                        unsigned mbar){
    asm volatile(
        "cp.async.bulk.shared::cluster.global.mbarrier::complete_tx::bytes "
        "[%0], [%1], %2, [%3];"
        :: "r"(dst), "l"(src), "r"(bytes), "r"(mbar) : "memory");
}
#define MBAR_INIT(addr, cnt) \
    asm volatile("mbarrier.init.shared.b64 [%0], %1;" :: "r"(addr), "r"(cnt) : "memory")
#define MBAR_EXPECT_TX(addr, bytes) \
    asm volatile("mbarrier.arrive.expect_tx.shared.b64 _, [%0], %1;" \
                 :: "r"(addr), "r"(bytes) : "memory")
#define MBAR_WAIT(mbar, parity) do {                                        \
    asm volatile(                                                           \
        "{\n\t.reg .pred P1;\n\t"                                           \
        "WL_%=:\n\t"                                                        \
        "mbarrier.try_wait.parity.acquire.cta.shared::cta.b64 P1, [%0], %1, 0x989680;\n\t" \
        "@P1 bra.uni WD_%=;\n\t"                                            \
        "bra.uni WL_%=;\n\t"                                                \
        "WD_%=:\n\t}"                                                       \
        :: "r"(mbar), "r"(parity) : "memory");                              \
} while (0)

// ---------------- fp32 -> fp16 hi/lo split into tiled+swizzled layout -------
__device__ __forceinline__ unsigned pack2hi(float a, float b){
    __half2 t = __halves2half2(__float2half_rn(a), __float2half_rn(b));
    return *(unsigned*)&t;
}
__device__ __forceinline__ unsigned pack2lo(float a, float b){
    float ha = __half2float(__float2half_rn(a));
    float hb = __half2float(__float2half_rn(b));
    __half2 t = __halves2half2(__float2half_rn(a - ha), __float2half_rn(b - hb));
    return *(unsigned*)&t;
}

// A-type: 128-row tiles of 128B rows (64 halves), SW128 swizzled, 16KB/tile.
// WLO=false skips the lo buffer (for 1-pass consumers).
template<bool WLO>
__global__ void split_tiled_A(const float* __restrict__ src,
                              __half* __restrict__ hi,
                              __half* __restrict__ lo,
                              int Mvalid, int Mpad, int K)
{
    const int id = blockIdx.x * 256 + threadIdx.x;
    const int CK = K >> 3;
    if (id >= Mpad * CK) return;
    const int m = id / CK, c = id % CK;
    float4 x0 = make_float4(0.f,0.f,0.f,0.f), x1 = x0;
    if (m < Mvalid) {
        const float4* s = (const float4*)(src + (size_t)m * K + c * 8);
        x0 = s[0]; x1 = s[1];
    }
    const size_t tile = (size_t)(m >> 7) * (K >> 6) + (c >> 3);
    const unsigned inner = (unsigned)((m & 127) * 128 + (((c & 7) * 16) ^ ((m & 7) * 16)));
    uint4 h = make_uint4(pack2hi(x0.x,x0.y), pack2hi(x0.z,x0.w),
                         pack2hi(x1.x,x1.y), pack2hi(x1.z,x1.w));
    *(uint4*)((char*)hi + tile * 16384 + inner) = h;
    if (WLO) {
        uint4 l = make_uint4(pack2lo(x0.x,x0.y), pack2lo(x0.z,x0.w),
                             pack2lo(x1.x,x1.y), pack2lo(x1.z,x1.w));
        *(uint4*)((char*)lo + tile * 16384 + inner) = l;
    }
}

// B-type split for all 5 weights in ONE launch: grid.y selects the weight.
__global__ void split_tiled_W(const float* __restrict__ s0, const float* __restrict__ s1,
                              const float* __restrict__ s2, const float* __restrict__ s3,
                              const float* __restrict__ s4,
                              __half* __restrict__ hiBase, __half* __restrict__ loBase)
{
    const int w = blockIdx.y;
    const float* src = (w == 0) ? s0 : (w == 1) ? s1 : (w == 2) ? s2 : (w == 3) ? s3 : s4;
    __half* hi = hiBase + (size_t)w * WELEM_;
    __half* lo = loBase + (size_t)w * WELEM_;

    const int id = blockIdx.x * 256 + threadIdx.x;
    const int CK = E_ >> 3;
    if (id >= E_ * CK) return;
    const int n = id / CK, c = id % CK;
    const float4* s = (const float4*)(src + (size_t)n * E_ + c * 8);
    float4 x0 = s[0], x1 = s[1];
    const size_t tile = (size_t)(n >> 8) * (E_ >> 6) + (c >> 3);
    const unsigned inner = (unsigned)((n & 255) * 128 + (((c & 7) * 16) ^ ((n & 7) * 16)));
    uint4 h = make_uint4(pack2hi(x0.x,x0.y), pack2hi(x0.z,x0.w),
                         pack2hi(x1.x,x1.y), pack2hi(x1.z,x1.w));
    uint4 l = make_uint4(pack2lo(x0.x,x0.y), pack2lo(x0.z,x0.w),
                         pack2lo(x1.x,x1.y), pack2lo(x1.z,x1.w));
    *(uint4*)((char*)hi + tile * 32768 + inner) = h;
    *(uint4*)((char*)lo + tile * 32768 + inner) = l;
}

__global__ void prep_scale_kernel(const float* __restrict__ pds, float* __restrict__ out)
{
    int d = threadIdx.x;
    if (d < D_) {
        float x = pds[d];
        float sp = (x > 20.f) ? x : log1pf(expf(x));
        out[d] = QSCALE_BASE * sp;
    }
}

// ============================================================================
// fp16 hi/lo tensor-core NT GEMM with cp.async.bulk tile loads.
// 128x256 CTA tile, 256 threads, warp tile 64x64, BK=64 halves,
// 2-stage mbarrier pipeline, m16n8k16 f16.
// NPASS=3: Ah*Bh + Al*Bh + Ah*Bl.  NPASS=2: Ah*Bh + Al*Bh.  NPASS=1: Ah*Bh.
// mode: 0 plain f32; 1 colscale f32; 2 const-scale f32.
// Piggyback: if A2h != null, grid-y row (gridDim.y-1) computes the secondary
// problem C2[M2,N] = A2 * B2^T (mode 0) — all of A, B, C, M swapped.
// ============================================================================
#define TILEA_B  16384
#define TILEB_B  32768
#define STB_     (2*TILEA_B + 2*TILEB_B)   // 98304 per stage
#define SMEM_GEMM_ (2*STB_ + 128)          // 196736

#define SOFF_AH_ 0
#define SOFF_AL_ TILEA_B
#define SOFF_BH_ (2*TILEA_B)
#define SOFF_BL_ (2*TILEA_B + TILEB_B)

template<int NPASS>
__global__ void __launch_bounds__(256)
gemm_bulk(const __half* __restrict__ Aht, const __half* __restrict__ Alt,
          const __half* __restrict__ Bht, const __half* __restrict__ Blt,
          float* __restrict__ C, int M, int N, int K,
          int mode, const float* __restrict__ colscale, float cscale,
          const __half* A2h, const __half* A2l,
          const __half* B2h, const __half* B2l, float* C2, int M2)
{
    extern __shared__ char smem[];
    const unsigned sb = (unsigned)__cvta_generic_to_shared(smem);
    const unsigned mb0 = sb + 2 * STB_;

    const int tid  = threadIdx.x;
    const int lane = tid & 31;
    const int warp = tid >> 5;
    const int wm = warp >> 2;
    const int wn = warp & 3;
    const int lr = lane >> 2;
    const int lc = lane & 3;

    // piggyback dispatch (uniform per CTA)
    int by = blockIdx.y;
    const __half* pAh = Aht; const __half* pAl = Alt;
    const __half* pBh = Bht; const __half* pBl = Blt;
    float* pC = C; int pM = M; int pmode = mode;
    if (A2h != nullptr && by == (int)gridDim.y - 1) {
        pAh = A2h; pAl = A2l; pBh = B2h; pBl = B2l;
        pC = C2; pM = M2; pmode = 0; by = 0;
    }

    const int KT = K >> 6;
    const int aTile = by * KT;
    const int bTile = blockIdx.x * KT;

    if (tid == 0) { MBAR_INIT(mb0, 1); MBAR_INIT(mb0 + 8, 1); }
    __syncthreads();

    float acc[4][8][4];
#pragma unroll
    for (int i = 0; i < 4; i++)
#pragma unroll
        for (int j = 0; j < 8; j++)
#pragma unroll
            for (int r = 0; r < 4; r++) acc[i][j][r] = 0.f;

    const int g  = lane >> 3;
    const int tr = lane & 7;
    unsigned aoff[4], aswz[4];
#pragma unroll
    for (int mt = 0; mt < 4; mt++) {
        const int row = wm * 64 + mt * 16 + (g & 1) * 8 + tr;
        aoff[mt] = (unsigned)(row * 128);
        aswz[mt] = (unsigned)((row & 7) * 16);
    }
    const unsigned alane = (unsigned)((g >> 1) * 16);
    unsigned boff[4], bswz[4];
#pragma unroll
    for (int n2 = 0; n2 < 4; n2++) {
        const int n = wn * 64 + n2 * 16 + (g >> 1) * 8 + tr;
        boff[n2] = (unsigned)(n * 128);
        bswz[n2] = (unsigned)((n & 7) * 16);
    }
    const unsigned blane = (unsigned)((g & 1) * 16);

    const unsigned stage_tx =
        (NPASS == 3) ? (unsigned)STB_ :
        (NPASS == 2) ? (unsigned)(STB_ - TILEB_B) :
                       (unsigned)(TILEA_B + TILEB_B);

    auto issue = [&](int it, int s){
        if (tid == 0) {
            const unsigned mb = mb0 + s * 8;
            MBAR_EXPECT_TX(mb, stage_tx);
            const unsigned dst = sb + s * STB_;
            bulk_cp(dst + SOFF_AH_, (const char*)pAh + (size_t)(aTile + it) * TILEA_B, TILEA_B, mb);
            if (NPASS >= 2)
                bulk_cp(dst + SOFF_AL_, (const char*)pAl + (size_t)(aTile + it) * TILEA_B, TILEA_B, mb);
            bulk_cp(dst + SOFF_BH_, (const char*)pBh + (size_t)(bTile + it) * TILEB_B, TILEB_B, mb);
            if (NPASS == 3)
                bulk_cp(dst + SOFF_BL_, (const char*)pBl + (size_t)(bTile + it) * TILEB_B, TILEB_B, mb);
        }
    };

    issue(0, 0);
    issue(1, 1);

    for (int it = 0; it < KT; it++) {
        const int s = it & 1;
        MBAR_WAIT(mb0 + s * 8, (unsigned)((it >> 1) & 1));

        const unsigned base = sb + s * STB_;
        const unsigned sAh = base + SOFF_AH_;
        const unsigned sAl = base + SOFF_AL_;
        const unsigned sBh = base + SOFF_BH_;
        const unsigned sBl = base + SOFF_BL_;

#pragma unroll
        for (int k0 = 0; k0 < 4; k0++) {
            const unsigned kb = (unsigned)(k0 * 32);

            unsigned ah[4][4], bh[4][4];
#pragma unroll
            for (int mt = 0; mt < 4; mt++)
                ldsm4(ah[mt], sAh + aoff[mt] + ((kb + alane) ^ aswz[mt]));
#pragma unroll
            for (int n2 = 0; n2 < 4; n2++)
                ldsm4(bh[n2], sBh + boff[n2] + ((kb + blane) ^ bswz[n2]));
#pragma unroll
            for (int mt = 0; mt < 4; mt++)
#pragma unroll
                for (int nt = 0; nt < 8; nt++)
                    mma_f16(acc[mt][nt], ah[mt][0], ah[mt][1], ah[mt][2], ah[mt][3],
                            bh[nt >> 1][(nt & 1) * 2], bh[nt >> 1][(nt & 1) * 2 + 1]);

            if (NPASS >= 2) {
                unsigned xl[4][4];
#pragma unroll
                for (int mt = 0; mt < 4; mt++)
                    ldsm4(xl[mt], sAl + aoff[mt] + ((kb + alane) ^ aswz[mt]));
#pragma unroll
                for (int mt = 0; mt < 4; mt++)
#pragma unroll
                    for (int nt = 0; nt < 8; nt++)
                        mma_f16(acc[mt][nt], xl[mt][0], xl[mt][1], xl[mt][2], xl[mt][3],
                                bh[nt >> 1][(nt & 1) * 2], bh[nt >> 1][(nt & 1) * 2 + 1]);

                if (NPASS == 3) {
#pragma unroll
                    for (int n2 = 0; n2 < 4; n2++)
                        ldsm4(xl[n2], sBl + boff[n2] + ((kb + blane) ^ bswz[n2]));
#pragma unroll
                    for (int mt = 0; mt < 4; mt++)
#pragma unroll
                        for (int nt = 0; nt < 8; nt++)
                            mma_f16(acc[mt][nt], ah[mt][0], ah[mt][1], ah[mt][2], ah[mt][3],
                                    xl[nt >> 1][(nt & 1) * 2], xl[nt >> 1][(nt & 1) * 2 + 1]);
                }
            }
        }
        __syncthreads();
        if (it + 2 < KT) issue(it + 2, s);
    }

    // --- epilogue ---
    const int bm = by * 128;
    const int bn = blockIdx.x * 256;
#pragma unroll
    for (int mt = 0; mt < 4; mt++) {
#pragma unroll
        for (int nt = 0; nt < 8; nt++) {
            const int r0 = bm + wm * 64 + mt * 16 + lr;
            const int c0 = bn + wn * 64 + nt * 8 + 2 * lc;
            float v0 = acc[mt][nt][0], v1 = acc[mt][nt][1];
            float v2 = acc[mt][nt][2], v3 = acc[mt][nt][3];
            if (pmode == 1) {
                const float s0 = colscale[c0 & (D_-1)], s1 = colscale[(c0+1) & (D_-1)];
                v0 *= s0; v1 *= s1; v2 *= s0; v3 *= s1;
            } else if (pmode == 2) {
                v0 *= cscale; v1 *= cscale; v2 *= cscale; v3 *= cscale;
            }
            if (r0 < pM)     *(float2*)(pC + (size_t)r0      * N + c0) = make_float2(v0, v1);
            if (r0 + 8 < pM) *(float2*)(pC + (size_t)(r0+8)  * N + c0) = make_float2(v2, v3);
        }
    }
}

// ---------------- chunked local attention (R10 structure) -------------------
__global__ void __launch_bounds__(384)
attn_kernel(const float* __restrict__ q, const float* __restrict__ k,
            const float* __restrict__ v, const float* __restrict__ relk,
            float* __restrict__ o, float* __restrict__ attn_out)
{
    __shared__ float sq[CHUNK_][129];
    __shared__ float sk[CTX_][129];
    __shared__ float sv[CTX_][129];
    __shared__ float sr[CTX_][129];
    __shared__ float sac[CHUNK_][CTX_];
    __shared__ float sbd[CHUNK_][CTX_];
    __shared__ float sw[CHUNK_][25];

    const int n = blockIdx.x, h = blockIdx.y, b = blockIdx.z;
    const int t = threadIdx.x;

    for (int i = t; i < CHUNK_ * D_; i += 384) {
        const int c = i >> 7, d = i & 127;
        const int s = n * CHUNK_ + c;
        sq[c][d] = q[((size_t)(b * S_ + s)) * E_ + h * D_ + d];
    }
    for (int i = t; i < CTX_ * D_; i += 384) {
        const int j = i >> 7, d = i & 127;
        const int s = n * CHUNK_ - 12 + j;
        float kv = 0.f, vv = 0.f;
        if (s >= 0 && s < S_) {
            const size_t base = ((size_t)(b * S_ + s)) * E_ + h * D_ + d;
            kv = k[base]; vv = v[base];
        }
        sk[j][d] = kv;
        sv[j][d] = vv;
        sr[j][d] = relk[(size_t)j * E_ + h * D_ + d];
    }
    __syncthreads();

    for (int i = t; i < CHUNK_ * CTX_; i += 384) {
        const int c = i / CTX_, j = i % CTX_;
        float a = 0.f, bb = 0.f;
#pragma unroll 8
        for (int d = 0; d < D_; d++) {
            const float qq = sq[c][d];
            a  = fmaf(qq, sk[j][d], a);
            bb = fmaf(qq, sr[j][d], bb);
        }
        sac[c][j] = a;
        sbd[c][j] = bb;
    }
    __syncthreads();

    for (int i = t; i < CHUNK_ * CTX_; i += 384) {
        const int c = i / CTX_, j = i % CTX_;
        const int idx = c * CTX_ + j;
        const int r = idx / (CTX_ + 1);
        const int p = idx % (CTX_ + 1);
        const float bd = (p < CTX_) ? sbd[r][p] : 0.f;
        float l = sac[c][j] + bd;
        l = 50.f * tanhf(l * 0.02f);
        sw[c][j] = l;
    }
    __syncthreads();

    if (t < CHUNK_) {
        const int c = t;
        float m = -1e30f;
        for (int j = 0; j < CTX_; j++) m = fmaxf(m, sw[c][j]);
        float sum = 0.f;
        for (int j = 0; j < CTX_; j++) { const float e = expf(sw[c][j] - m); sum += e; sw[c][j] = e; }
        const float inv = 1.f / sum;
        for (int j = 0; j < CTX_; j++) sw[c][j] *= inv;
    }
    __syncthreads();

    if (attn_out) {
        for (int i = t; i < CHUNK_ * CTX_; i += 384) {
            const int c = i / CTX_, j = i % CTX_;
            attn_out[((((size_t)b * H_ + h) * NB_ + n) * CHUNK_ + c) * CTX_ + j] = sw[c][j];
        }
    }

    for (int i = t; i < CHUNK_ * D_; i += 384) {
        const int c = i >> 7, d = i & 127;
        float acc = 0.f;
#pragma unroll
        for (int j = 0; j < CTX_; j++) acc = fmaf(sw[c][j], sv[j][d], acc);
        o[((size_t)(b * S_ + n * CHUNK_ + c)) * E_ + h * D_ + d] = acc;
    }
}

// ---------------- launch -----------------------------------------------------
extern "C" void kernel_launch(void* const* d_in, const int* in_sizes, int n_in,
                              void* d_out, int out_size)
{
    const float* hs   = (const float*)d_in[0];
    const float* pe   = (const float*)d_in[1];
    const float* w_q  = (const float*)d_in[2];
    const float* w_k  = (const float*)d_in[3];
    const float* w_v  = (const float*)d_in[4];
    const float* w_p  = (const float*)d_in[5];
    const float* w_r  = (const float*)d_in[6];
    const float* pds  = (const float*)d_in[7];
    float* out = (float*)d_out;

    float *q, *k, *v, *o, *rk, *qs;
    cudaGetSymbolAddress((void**)&q,  g_q);
    cudaGetSymbolAddress((void**)&k,  g_k);
    cudaGetSymbolAddress((void**)&v,  g_v);
    cudaGetSymbolAddress((void**)&o,  g_o);
    cudaGetSymbolAddress((void**)&rk, g_relk);
    cudaGetSymbolAddress((void**)&qs, g_qdscale);

    __half *hsh, *hsl, *och, *ocl, *wh, *wl, *peh, *pel;
    cudaGetSymbolAddress((void**)&hsh, g_hs_hi);
    cudaGetSymbolAddress((void**)&hsl, g_hs_lo);
    cudaGetSymbolAddress((void**)&och, g_oc_hi);
    cudaGetSymbolAddress((void**)&ocl, g_oc_lo);
    cudaGetSymbolAddress((void**)&wh,  g_w_hi);
    cudaGetSymbolAddress((void**)&wl,  g_w_lo);
    cudaGetSymbolAddress((void**)&peh, g_pe_hi);
    cudaGetSymbolAddress((void**)&pel, g_pe_lo);

    cudaFuncSetAttribute(gemm_bulk<3>, cudaFuncAttributeMaxDynamicSharedMemorySize, SMEM_GEMM_);
    cudaFuncSetAttribute(gemm_bulk<2>, cudaFuncAttributeMaxDynamicSharedMemorySize, SMEM_GEMM_);
    cudaFuncSetAttribute(gemm_bulk<1>, cudaFuncAttributeMaxDynamicSharedMemorySize, SMEM_GEMM_);

    prep_scale_kernel<<<1, 128>>>(pds, qs);

    const int tA = MTOK_ * (E_ / 8);
    split_tiled_A<true><<<(tA + 255) / 256, 256>>>(hs, hsh, hsl, MTOK_, MTOK_, E_);
    const int tB = E_ * (E_ / 8);
    split_tiled_W<<<dim3((tB + 255) / 256, 5), 256>>>(w_q, w_k, w_v, w_p, w_r, wh, wl);
    const int tPE = 128 * (E_ / 8);
    split_tiled_A<true><<<(tPE + 255) / 256, 256>>>(pe, peh, pel, CTX_, 128, E_);

    const dim3 gK(E_ / 256, MTOK_ / 128 + 1);   // (6, 193) — last row = rel GEMM
    const dim3 gBig(E_ / 256, MTOK_ / 128);     // (6, 192)

    // q: 2-pass (A exact, B fp16) — logit-side error budget analyzed above.
    gemm_bulk<2><<<gBig, 256, SMEM_GEMM_>>>(hsh, hsl, wh + 0*(size_t)WELEM_, wl + 0*(size_t)WELEM_,
                                            q, MTOK_, E_, E_, 1, qs, 1.f,
                                            nullptr, nullptr, nullptr, nullptr, nullptr, 0);
    // k: 3-pass, carrying the rel GEMM piggyback (also 3-pass).
    gemm_bulk<3><<<gK, 256, SMEM_GEMM_>>>(hsh, hsl, wh + 1*(size_t)WELEM_, wl + 1*(size_t)WELEM_,
                                          k, MTOK_, E_, E_, 2, nullptr, KSCALE,
                                          peh, pel,
                                          wh + 4*(size_t)WELEM_, wl + 4*(size_t)WELEM_,
                                          rk, CTX_);
    gemm_bulk<1><<<gBig, 256, SMEM_GEMM_>>>(hsh, hsl, wh + 2*(size_t)WELEM_, wl + 2*(size_t)WELEM_,
                                            v, MTOK_, E_, E_, 0, nullptr, 1.f,
                                            nullptr, nullptr, nullptr, nullptr, nullptr, 0);

    float* attn = ((size_t)out_size >= OUT_MAIN + ATTN_SZ) ? (out + OUT_MAIN) : nullptr;
    attn_kernel<<<dim3(NB_, H_, B_), 384>>>(q, k, v, rk, o, attn);

    split_tiled_A<false><<<(tA + 255) / 256, 256>>>(o, och, ocl, MTOK_, MTOK_, E_);
    gemm_bulk<1><<<gBig, 256, SMEM_GEMM_>>>(och, ocl, wh + 3*(size_t)WELEM_, wl + 3*(size_t)WELEM_,
                                            out, MTOK_, E_, E_, 0, nullptr, 1.f,
                                            nullptr, nullptr, nullptr, nullptr, nullptr, 0);
}